// round 14
// baseline (speedup 1.0000x reference)
#include <cuda_runtime.h>
#include <cuda_fp16.h>
#include <math.h>

// Problem constants
#define D_  768
#define H_  12
#define E_  64
#define S_  2000
#define MQ  2048
#define BLn 256
#define TQn 8
#define NSPLIT 3

// Scratch (device globals)
__device__ __half g_Xq[MQ * D_];
__device__ __half g_Xk[S_ * D_];
__device__ __half g_Xv[S_ * D_];
__device__ __half g_Wh[4 * D_ * D_];   // half weights Wq,Wk,Wv,Wo
__device__ __half g_Qb[MQ * D_];
__device__ __half g_Kb[S_ * D_];
__device__ __half g_Vb[S_ * D_];
__device__ __half g_Oacc[NSPLIT * MQ * D_];
__device__ float  g_ML[NSPLIT * MQ * H_ * 2];
__device__ __half g_Pool[BLn * D_];

// ---------------------------------------------------------------------------
// helpers
// ---------------------------------------------------------------------------
__device__ __forceinline__ void mma_f16(float* d, const unsigned* a,
                                        unsigned b0, unsigned b1) {
    asm volatile(
        "mma.sync.aligned.m16n8k16.row.col.f32.f16.f16.f32 "
        "{%0,%1,%2,%3},{%4,%5,%6,%7},{%8,%9},{%0,%1,%2,%3};\n"
        : "+f"(d[0]), "+f"(d[1]), "+f"(d[2]), "+f"(d[3])
        : "r"(a[0]), "r"(a[1]), "r"(a[2]), "r"(a[3]), "r"(b0), "r"(b1));
}

__device__ __forceinline__ unsigned packh2(float x, float y) {
    __half2 h = __floats2half2_rn(x, y);
    return *reinterpret_cast<unsigned*>(&h);
}

__device__ __forceinline__ void cp8(unsigned* dst_smem, const void* src, bool valid) {
    unsigned d = (unsigned)__cvta_generic_to_shared(dst_smem);
    int sz = valid ? 8 : 0;
    asm volatile("cp.async.ca.shared.global [%0], [%1], 8, %2;\n"
                 :: "r"(d), "l"(src), "r"(sz));
}
__device__ __forceinline__ void cp_commit() {
    asm volatile("cp.async.commit_group;\n");
}
template <int N>
__device__ __forceinline__ void cp_wait() {
    asm volatile("cp.async.wait_group %0;\n" :: "n"(N));
}

// ---------------------------------------------------------------------------
// Weight conversion fp32 -> half (one-time)
// ---------------------------------------------------------------------------
__global__ void conv_w_kernel(const float* W0, const float* W1,
                              const float* W2, const float* W3,
                              __half* dst) {
    int z = blockIdx.y;
    const float* s = (z == 0) ? W0 : (z == 1) ? W1 : (z == 2) ? W2 : W3;
    int i = blockIdx.x * 256 + threadIdx.x;
    if (i < D_ * D_)
        dst[(size_t)z * D_ * D_ + i] = __float2half_rn(s[i]);
}

// ---------------------------------------------------------------------------
// Fused LayerNorm -> half outputs
// ---------------------------------------------------------------------------
__global__ void ln3_kernel(const float* __restrict__ tgt, __half* __restrict__ Xq,
                           const float* __restrict__ gq, const float* __restrict__ bq_,
                           const float* __restrict__ key, const float* __restrict__ val,
                           __half* __restrict__ Xk, __half* __restrict__ Xv,
                           const float* __restrict__ gkv, const float* __restrict__ bkv) {
    int row = blockIdx.x;
    const float *x, *g, *b;
    __half* y;
    if (row < MQ) {
        x = tgt + (size_t)row * D_; y = Xq + (size_t)row * D_; g = gq; b = bq_;
    } else if (row < MQ + S_) {
        int r = row - MQ;
        x = key + (size_t)r * D_; y = Xk + (size_t)r * D_; g = gkv; b = bkv;
    } else {
        int r = row - MQ - S_;
        x = val + (size_t)r * D_; y = Xv + (size_t)r * D_; g = gkv; b = bkv;
    }

    int t = threadIdx.x;
    float v0 = x[t], v1 = x[t + 256], v2 = x[t + 512];
    float s  = v0 + v1 + v2;
    float ss = v0 * v0 + v1 * v1 + v2 * v2;

    __shared__ float redS[8], redQ[8];
    #pragma unroll
    for (int o = 16; o > 0; o >>= 1) {
        s  += __shfl_xor_sync(0xffffffffu, s, o);
        ss += __shfl_xor_sync(0xffffffffu, ss, o);
    }
    int warp = t >> 5, lane = t & 31;
    if (lane == 0) { redS[warp] = s; redQ[warp] = ss; }
    __syncthreads();
    float sum = 0.f, sq = 0.f;
    #pragma unroll
    for (int w = 0; w < 8; w++) { sum += redS[w]; sq += redQ[w]; }

    float mean = sum * (1.0f / D_);
    float var  = sq * (1.0f / D_) - mean * mean;
    float rs   = rsqrtf(var + 1e-5f);

    y[t]       = __float2half_rn((v0 - mean) * rs * g[t]       + b[t]);
    y[t + 256] = __float2half_rn((v1 - mean) * rs * g[t + 256] + b[t + 256]);
    y[t + 512] = __float2half_rn((v2 - mean) * rs * g[t + 512] + b[t + 512]);
}

// ---------------------------------------------------------------------------
// Batched FP16 GEMM: C[M][768] = A(half) @ W(half)^T + bias
// 128x128 tile, BK=32, 256 threads, warp tile 64x32; m16n8k16 fp16 mma.
// As/Ws: half2 rows, stride 20 words; uint4-aligned staging (80r+16ch ≡ 0 mod 16).
// cvtOut=1 -> half output; 0 -> fp32 output.
// ---------------------------------------------------------------------------
#define GST 20
__global__ __launch_bounds__(256, 2)
void gemm3_f16(const __half* A0, const __half* W0, const float* bi0, void* C0, int M0,
               const __half* A1, const __half* W1, const float* bi1, void* C1, int M1,
               const __half* A2, const __half* W2, const float* bi2, void* C2, int M2,
               int cvtOut) {
    const __half* A; const __half* W; const float* bias; void* C; int M;
    if (blockIdx.z == 0) { A = A0; W = W0; bias = bi0; C = C0; M = M0; }
    else if (blockIdx.z == 1) { A = A1; W = W1; bias = bi1; C = C1; M = M1; }
    else { A = A2; W = W2; bias = bi2; C = C2; M = M2; }

    __shared__ unsigned As[128 * GST];
    __shared__ unsigned Ws[128 * GST];

    int t = threadIdx.x, w = t >> 5, lane = t & 31;
    int g = lane >> 2, c = lane & 3;
    int wm = w >> 2, wn = w & 3;
    int row0 = blockIdx.y * 128;
    int col0 = blockIdx.x * 128;

    float acc[4][4][4];
    #pragma unroll
    for (int i = 0; i < 4; i++)
        #pragma unroll
        for (int j = 0; j < 4; j++)
            #pragma unroll
            for (int k = 0; k < 4; k++) acc[i][j][k] = 0.f;

    for (int k0 = 0; k0 < D_; k0 += 32) {
        __syncthreads();
        // A and W: 128 rows x 32 halves each; 512 uint4 items each
        #pragma unroll
        for (int i = t; i < 512; i += 256) {
            int r = i >> 2, ch = i & 3;
            int ar = row0 + r;
            uint4 av = make_uint4(0u, 0u, 0u, 0u);
            if (ar < M) av = *(const uint4*)(A + (size_t)ar * D_ + k0 + ch * 8);
            *(uint4*)&As[r * GST + ch * 4] = av;

            uint4 wv = *(const uint4*)(W + (size_t)(col0 + r) * D_ + k0 + ch * 8);
            *(uint4*)&Ws[r * GST + ch * 4] = wv;
        }
        __syncthreads();

        #pragma unroll
        for (int ks = 0; ks < 2; ks++) {
            int kk = ks * 8;
            unsigned a[4][4];
            #pragma unroll
            for (int mt = 0; mt < 4; mt++) {
                int base = wm * 64 + mt * 16;
                a[mt][0] = As[(base + g)     * GST + kk + c];
                a[mt][1] = As[(base + g + 8) * GST + kk + c];
                a[mt][2] = As[(base + g)     * GST + kk + 4 + c];
                a[mt][3] = As[(base + g + 8) * GST + kk + 4 + c];
            }
            #pragma unroll
            for (int nt = 0; nt < 4; nt++) {
                int n = wn * 32 + nt * 8 + g;
                unsigned b0 = Ws[n * GST + kk + c];
                unsigned b1 = Ws[n * GST + kk + 4 + c];
                #pragma unroll
                for (int mt = 0; mt < 4; mt++)
                    mma_f16(acc[mt][nt], a[mt], b0, b1);
            }
        }
    }

    #pragma unroll
    for (int mt = 0; mt < 4; mt++) {
        int rA = row0 + wm * 64 + mt * 16 + g;
        int rB = rA + 8;
        #pragma unroll
        for (int nt = 0; nt < 4; nt++) {
            int colb = col0 + wn * 32 + nt * 8 + 2 * c;
            float b0v = bias[colb], b1v = bias[colb + 1];
            float v00 = acc[mt][nt][0] + b0v, v01 = acc[mt][nt][1] + b1v;
            float v10 = acc[mt][nt][2] + b0v, v11 = acc[mt][nt][3] + b1v;
            if (cvtOut) {
                __half* Ch = (__half*)C;
                if (rA < M) *(unsigned*)&Ch[(size_t)rA * D_ + colb] = packh2(v00, v01);
                if (rB < M) *(unsigned*)&Ch[(size_t)rB * D_ + colb] = packh2(v10, v11);
            } else {
                float* Cf = (float*)C;
                if (rA < M) *(float2*)&Cf[(size_t)rA * D_ + colb] = make_float2(v00, v01);
                if (rB < M) *(float2*)&Cf[(size_t)rB * D_ + colb] = make_float2(v10, v11);
            }
        }
    }
}

// ---------------------------------------------------------------------------
// FP16 flash attention (R13 verbatim except half Oacc epilogue)
// ---------------------------------------------------------------------------
#define AQT 256
#define ASC 32
#define NCH ((S_ + ASC - 1) / ASC)
#define CHSPLIT ((NCH + NSPLIT - 1) / NSPLIT)
#define QST 36
#define KST 36
#define VST 20
#define KBUF (ASC * KST)
#define VBUF (E_ * VST)
#define ATTN_WORDS (AQT*QST + 2*KBUF + 2*VBUF + CHSPLIT*ASC)
#define ATTN_SMEM  (ATTN_WORDS * 4)

__global__ __launch_bounds__(256, 2)
void attn_f16(const __half* __restrict__ Q, const __half* __restrict__ K,
              const __half* __restrict__ V, const int* __restrict__ mask,
              __half* __restrict__ Oacc, float* __restrict__ ML) {
    extern __shared__ unsigned smu[];
    unsigned* Qs = smu;                        // [256][36]
    unsigned* Ks0 = Qs + AQT * QST;            // 2 x [32][36]
    unsigned* Vt0 = Ks0 + 2 * KBUF;            // 2 x [64 e][20]
    float* maskSm = (float*)(Vt0 + 2 * VBUF);  // [CHSPLIT*32]

    int h = blockIdx.y;
    int z = blockIdx.z;
    int row0 = blockIdx.x * AQT;
    int t = threadIdx.x, w = t >> 5, lane = t & 31;
    int g = lane >> 2, c = lane & 3;
    int wrow = w * 32;

    int chBeg = z * CHSPLIT;
    int chEnd = min(chBeg + CHSPLIT, NCH);

    #pragma unroll 4
    for (int i = t; i < AQT * 8; i += 256) {
        int r = i >> 3, part = i & 7;
        uint4 q4 = *(const uint4*)(Q + (size_t)(row0 + r) * D_ + h * E_ + part * 8);
        *(uint4*)&Qs[r * QST + part * 4] = q4;
    }
    for (int i = t; i < CHSPLIT * ASC; i += 256) {
        int gs = chBeg * ASC + i;
        maskSm[i] = (gs < S_ && mask[gs] != 0) ? 0.f : -1e30f;
    }

    auto stageK = [&](int ch, int buf) {
        unsigned* Ks = Ks0 + buf * KBUF;
        int s0 = ch * ASC;
        #pragma unroll
        for (int i = t; i < ASC * 16; i += 256) {
            int s = i >> 4, chk = i & 15;
            int gs = s0 + s;
            cp8(&Ks[s * KST + chk * 2],
                K + (size_t)gs * D_ + h * E_ + chk * 4, gs < S_);
        }
        cp_commit();
    };
    auto loadV = [&](int ch) -> uint4 {
        int gs = ch * ASC + lane;
        if (gs < S_)
            return *(const uint4*)(V + (size_t)gs * D_ + h * E_ + w * 8);
        return make_uint4(0u, 0u, 0u, 0u);
    };
    auto storeV = [&](uint4 v, int buf) {
        __half* Vth = (__half*)(Vt0 + buf * VBUF);
        const __half* hv = (const __half*)&v;
        #pragma unroll
        for (int j = 0; j < 8; j++)
            Vth[(w * 8 + j) * (VST * 2) + lane] = hv[j];
    };

    float mA[2] = {-1e30f, -1e30f}, mB[2] = {-1e30f, -1e30f};
    float lA[2] = {0.f, 0.f}, lB[2] = {0.f, 0.f};
    float acc[2][8][4];
    #pragma unroll
    for (int mt = 0; mt < 2; mt++)
        #pragma unroll
        for (int nt = 0; nt < 8; nt++)
            #pragma unroll
            for (int k = 0; k < 4; k++) acc[mt][nt][k] = 0.f;

    {
        uint4 v0 = loadV(chBeg);
        stageK(chBeg, 0);
        cp_wait<0>();
        storeV(v0, 0);
    }
    __syncthreads();

    for (int ch = chBeg; ch < chEnd; ch++) {
        int buf = (ch - chBeg) & 1;
        bool more = (ch + 1 < chEnd);
        uint4 vnext;
        if (more) {
            vnext = loadV(ch + 1);
            stageK(ch + 1, buf ^ 1);
        }

        const unsigned* Ks = Ks0 + buf * KBUF;
        const unsigned* Vt = Vt0 + buf * VBUF;
        const float* maskAdd = maskSm + (ch - chBeg) * ASC;

        float sc[2][4][4];
        #pragma unroll
        for (int mt = 0; mt < 2; mt++)
            #pragma unroll
            for (int nt = 0; nt < 4; nt++)
                #pragma unroll
                for (int k = 0; k < 4; k++) sc[mt][nt][k] = 0.f;

        #pragma unroll
        for (int ks = 0; ks < 4; ks++) {
            int kk = ks * 8;
            unsigned a[2][4];
            #pragma unroll
            for (int mt = 0; mt < 2; mt++) {
                int base = wrow + mt * 16;
                a[mt][0] = Qs[(base + g)     * QST + kk + c];
                a[mt][1] = Qs[(base + g + 8) * QST + kk + c];
                a[mt][2] = Qs[(base + g)     * QST + kk + 4 + c];
                a[mt][3] = Qs[(base + g + 8) * QST + kk + 4 + c];
            }
            #pragma unroll
            for (int nt = 0; nt < 4; nt++) {
                int n0 = nt * 8;
                unsigned b0 = Ks[(n0 + g) * KST + kk + c];
                unsigned b1 = Ks[(n0 + g) * KST + kk + 4 + c];
                mma_f16(sc[0][nt], a[0], b0, b1);
                mma_f16(sc[1][nt], a[1], b0, b1);
            }
        }

        #pragma unroll
        for (int mt = 0; mt < 2; mt++) {
            float mxA = -1e30f, mxB = -1e30f;
            #pragma unroll
            for (int nt = 0; nt < 4; nt++) {
                int j0 = nt * 8 + 2 * c;
                float ma0 = maskAdd[j0], ma1 = maskAdd[j0 + 1];
                sc[mt][nt][0] = sc[mt][nt][0] * 0.125f + ma0;
                sc[mt][nt][1] = sc[mt][nt][1] * 0.125f + ma1;
                sc[mt][nt][2] = sc[mt][nt][2] * 0.125f + ma0;
                sc[mt][nt][3] = sc[mt][nt][3] * 0.125f + ma1;
                mxA = fmaxf(mxA, fmaxf(sc[mt][nt][0], sc[mt][nt][1]));
                mxB = fmaxf(mxB, fmaxf(sc[mt][nt][2], sc[mt][nt][3]));
            }
            mxA = fmaxf(mxA, __shfl_xor_sync(0xffffffffu, mxA, 1));
            mxA = fmaxf(mxA, __shfl_xor_sync(0xffffffffu, mxA, 2));
            mxB = fmaxf(mxB, __shfl_xor_sync(0xffffffffu, mxB, 1));
            mxB = fmaxf(mxB, __shfl_xor_sync(0xffffffffu, mxB, 2));

            float mnA = fmaxf(mA[mt], mxA);
            float mnB = fmaxf(mB[mt], mxB);
            float corrA = __expf(mA[mt] - mnA);
            float corrB = __expf(mB[mt] - mnB);
            mA[mt] = mnA; mB[mt] = mnB;

            float psA = 0.f, psB = 0.f;
            #pragma unroll
            for (int nt = 0; nt < 4; nt++) {
                float p0 = __expf(sc[mt][nt][0] - mnA);
                float p1 = __expf(sc[mt][nt][1] - mnA);
                float p2 = __expf(sc[mt][nt][2] - mnB);
                float p3 = __expf(sc[mt][nt][3] - mnB);
                psA += p0 + p1; psB += p2 + p3;
                sc[mt][nt][0] = p0; sc[mt][nt][1] = p1;
                sc[mt][nt][2] = p2; sc[mt][nt][3] = p3;
            }
            psA += __shfl_xor_sync(0xffffffffu, psA, 1);
            psA += __shfl_xor_sync(0xffffffffu, psA, 2);
            psB += __shfl_xor_sync(0xffffffffu, psB, 1);
            psB += __shfl_xor_sync(0xffffffffu, psB, 2);
            lA[mt] = lA[mt] * corrA + psA;
            lB[mt] = lB[mt] * corrB + psB;
            #pragma unroll
            for (int nt = 0; nt < 8; nt++) {
                acc[mt][nt][0] *= corrA; acc[mt][nt][1] *= corrA;
                acc[mt][nt][2] *= corrB; acc[mt][nt][3] *= corrB;
            }
        }

        #pragma unroll
        for (int ks = 0; ks < 2; ks++) {
            int kk = ks * 8;
            int t0 = ks * 2, t1 = t0 + 1;
            unsigned aP[2][4];
            #pragma unroll
            for (int mt = 0; mt < 2; mt++) {
                aP[mt][0] = packh2(sc[mt][t0][0], sc[mt][t0][1]);
                aP[mt][1] = packh2(sc[mt][t0][2], sc[mt][t0][3]);
                aP[mt][2] = packh2(sc[mt][t1][0], sc[mt][t1][1]);
                aP[mt][3] = packh2(sc[mt][t1][2], sc[mt][t1][3]);
            }
            #pragma unroll
            for (int nt = 0; nt < 8; nt++) {
                int e0 = nt * 8;
                unsigned b0 = Vt[(e0 + g) * VST + kk + c];
                unsigned b1 = Vt[(e0 + g) * VST + kk + 4 + c];
                mma_f16(acc[0][nt], aP[0], b0, b1);
                mma_f16(acc[1][nt], aP[1], b0, b1);
            }
        }

        if (more) {
            cp_wait<0>();
            storeV(vnext, buf ^ 1);
        }
        __syncthreads();
    }

    // epilogue: half unnormalized acc + fp32 (m,l)
    #pragma unroll
    for (int mt = 0; mt < 2; mt++) {
        int rA = row0 + wrow + mt * 16 + g;
        int rB = rA + 8;
        __half* obase = Oacc + (size_t)z * MQ * D_;
        #pragma unroll
        for (int nt = 0; nt < 8; nt++) {
            int col = h * E_ + nt * 8 + 2 * c;
            *(unsigned*)&obase[(size_t)rA * D_ + col] = packh2(acc[mt][nt][0], acc[mt][nt][1]);
            *(unsigned*)&obase[(size_t)rB * D_ + col] = packh2(acc[mt][nt][2], acc[mt][nt][3]);
        }
        if (c == 0) {
            size_t iA = ((size_t)(z * MQ + rA) * H_ + h) * 2;
            size_t iB = ((size_t)(z * MQ + rB) * H_ + h) * 2;
            ML[iA]     = mA[mt]; ML[iA + 1] = lA[mt];
            ML[iB]     = mB[mt]; ML[iB + 1] = lB[mt];
        }
    }
}

// ---------------------------------------------------------------------------
// Split-KV combine + mean-pool (scalar, 768 blocks); half Oacc in, half out
// ---------------------------------------------------------------------------
__global__ void combine_pool_kernel(const __half* __restrict__ Oacc,
                                    const float* __restrict__ ML,
                                    __half* __restrict__ P) {
    int idx = blockIdx.x * 256 + threadIdx.x;
    if (idx >= BLn * D_) return;
    int bl = idx / D_, d = idx % D_;
    int h = d >> 6;
    float s = 0.f;
    #pragma unroll
    for (int tq = 0; tq < TQn; tq++) {
        int row = bl * TQn + tq;
        size_t i0 = ((size_t)(0 * MQ + row) * H_ + h) * 2;
        size_t i1 = ((size_t)(1 * MQ + row) * H_ + h) * 2;
        size_t i2 = ((size_t)(2 * MQ + row) * H_ + h) * 2;
        float m0 = ML[i0], l0 = ML[i0 + 1];
        float m1 = ML[i1], l1 = ML[i1 + 1];
        float m2 = ML[i2], l2 = ML[i2 + 1];
        float M = fmaxf(m0, fmaxf(m1, m2));
        float w0 = __expf(m0 - M), w1 = __expf(m1 - M), w2 = __expf(m2 - M);
        float denom = l0 * w0 + l1 * w1 + l2 * w2;
        float a0 = __half2float(Oacc[(size_t)(0 * MQ + row) * D_ + d]);
        float a1 = __half2float(Oacc[(size_t)(1 * MQ + row) * D_ + d]);
        float a2 = __half2float(Oacc[(size_t)(2 * MQ + row) * D_ + d]);
        s += (a0 * w0 + a1 * w1 + a2 * w2) / denom;
    }
    P[idx] = __float2half_rn(s * (1.0f / TQn));
}

// ---------------------------------------------------------------------------
extern "C" void kernel_launch(void* const* d_in, const int* in_sizes, int n_in,
                              void* d_out, int out_size) {
    const float* target     = (const float*)d_in[0];
    const float* key_bank   = (const float*)d_in[1];
    const float* value_bank = (const float*)d_in[2];
    const int*   bank_mask  = (const int*)  d_in[3];
    const float* Wq = (const float*)d_in[4];
    const float* bq = (const float*)d_in[5];
    const float* Wk = (const float*)d_in[6];
    const float* bk = (const float*)d_in[7];
    const float* Wv = (const float*)d_in[8];
    const float* bv = (const float*)d_in[9];
    const float* Wo = (const float*)d_in[10];
    const float* bo = (const float*)d_in[11];
    const float* gq = (const float*)d_in[12];
    const float* betaq = (const float*)d_in[13];
    const float* gkv = (const float*)d_in[14];
    const float* betakv = (const float*)d_in[15];
    float* out = (float*)d_out;

    __half *Xq, *Xk, *Xv, *Wh, *Qb, *Kb, *Vb, *Oacc, *Pool;
    float *ML;
    cudaGetSymbolAddress((void**)&Xq,  g_Xq);
    cudaGetSymbolAddress((void**)&Xk,  g_Xk);
    cudaGetSymbolAddress((void**)&Xv,  g_Xv);
    cudaGetSymbolAddress((void**)&Wh,  g_Wh);
    cudaGetSymbolAddress((void**)&Qb,  g_Qb);
    cudaGetSymbolAddress((void**)&Kb,  g_Kb);
    cudaGetSymbolAddress((void**)&Vb,  g_Vb);
    cudaGetSymbolAddress((void**)&Oacc, g_Oacc);
    cudaGetSymbolAddress((void**)&ML,  g_ML);
    cudaGetSymbolAddress((void**)&Pool, g_Pool);

    cudaFuncSetAttribute(attn_f16,
                         cudaFuncAttributeMaxDynamicSharedMemorySize, ATTN_SMEM);

    // 0. Convert weights to half (one-time per launch)
    conv_w_kernel<<<dim3((D_ * D_ + 255) / 256, 4), 256>>>(Wq, Wk, Wv, Wo, Wh);

    // 1. Fused LayerNorms (half outputs)
    ln3_kernel<<<MQ + 2 * S_, 256>>>(target, Xq, gq, betaq,
                                     key_bank, value_bank, Xk, Xv, gkv, betakv);

    // 2. Q/K/V projections (half weights + outputs)
    gemm3_f16<<<dim3(D_ / 128, 16, 3), 256>>>(
        Xq, Wh + 0 * D_ * D_, bq, Qb, MQ,
        Xk, Wh + 1 * D_ * D_, bk, Kb, S_,
        Xv, Wh + 2 * D_ * D_, bv, Vb, S_, 1);

    // 3. Attention: fp16 mma, split-KV x3, one wave; half Oacc
    attn_f16<<<dim3(MQ / AQT, H_, NSPLIT), 256, ATTN_SMEM>>>(
        Qb, Kb, Vb, bank_mask, Oacc, ML);

    // 4. Combine + mean-pool (half in/out)
    combine_pool_kernel<<<(BLn * D_ + 255) / 256, 256>>>(Oacc, ML, Pool);

    // 5. Output projection (fp32 out)
    gemm3_f16<<<dim3(D_ / 128, 2, 1), 256>>>(
        Pool, Wh + 3 * D_ * D_, bo, out, BLn,
        Pool, Wh + 3 * D_ * D_, bo, out, BLn,
        Pool, Wh + 3 * D_ * D_, bo, out, BLn, 0);
}

// round 15
// speedup vs baseline: 1.0275x; 1.0275x over previous
#include <cuda_runtime.h>
#include <cuda_fp16.h>
#include <math.h>

// Problem constants
#define D_  768
#define H_  12
#define E_  64
#define S_  2000
#define MQ  2048
#define BLn 256
#define TQn 8
#define NSPLIT 3

// Scratch (device globals)
__device__ __half g_Xq[MQ * D_];
__device__ __half g_Xk[S_ * D_];
__device__ __half g_Xv[S_ * D_];
__device__ __half g_Qb[MQ * D_];
__device__ __half g_Kb[S_ * D_];
__device__ __half g_Vb[S_ * D_];
__device__ __half g_Oacc[NSPLIT * MQ * D_];
__device__ float  g_ML[NSPLIT * MQ * H_ * 2];
__device__ __half g_Pool[BLn * D_];

// ---------------------------------------------------------------------------
// helpers
// ---------------------------------------------------------------------------
__device__ __forceinline__ void mma_f16(float* d, const unsigned* a,
                                        unsigned b0, unsigned b1) {
    asm volatile(
        "mma.sync.aligned.m16n8k16.row.col.f32.f16.f16.f32 "
        "{%0,%1,%2,%3},{%4,%5,%6,%7},{%8,%9},{%0,%1,%2,%3};\n"
        : "+f"(d[0]), "+f"(d[1]), "+f"(d[2]), "+f"(d[3])
        : "r"(a[0]), "r"(a[1]), "r"(a[2]), "r"(a[3]), "r"(b0), "r"(b1));
}

__device__ __forceinline__ unsigned packh2(float x, float y) {
    __half2 h = __floats2half2_rn(x, y);
    return *reinterpret_cast<unsigned*>(&h);
}

__device__ __forceinline__ void cp8(unsigned* dst_smem, const void* src, bool valid) {
    unsigned d = (unsigned)__cvta_generic_to_shared(dst_smem);
    int sz = valid ? 8 : 0;
    asm volatile("cp.async.ca.shared.global [%0], [%1], 8, %2;\n"
                 :: "r"(d), "l"(src), "r"(sz));
}
__device__ __forceinline__ void cp_commit() {
    asm volatile("cp.async.commit_group;\n");
}
template <int N>
__device__ __forceinline__ void cp_wait() {
    asm volatile("cp.async.wait_group %0;\n" :: "n"(N));
}

// ---------------------------------------------------------------------------
// Fused LayerNorm -> half outputs
// ---------------------------------------------------------------------------
__global__ void ln3_kernel(const float* __restrict__ tgt, __half* __restrict__ Xq,
                           const float* __restrict__ gq, const float* __restrict__ bq_,
                           const float* __restrict__ key, const float* __restrict__ val,
                           __half* __restrict__ Xk, __half* __restrict__ Xv,
                           const float* __restrict__ gkv, const float* __restrict__ bkv) {
    int row = blockIdx.x;
    const float *x, *g, *b;
    __half* y;
    if (row < MQ) {
        x = tgt + (size_t)row * D_; y = Xq + (size_t)row * D_; g = gq; b = bq_;
    } else if (row < MQ + S_) {
        int r = row - MQ;
        x = key + (size_t)r * D_; y = Xk + (size_t)r * D_; g = gkv; b = bkv;
    } else {
        int r = row - MQ - S_;
        x = val + (size_t)r * D_; y = Xv + (size_t)r * D_; g = gkv; b = bkv;
    }

    int t = threadIdx.x;
    float v0 = x[t], v1 = x[t + 256], v2 = x[t + 512];
    float s  = v0 + v1 + v2;
    float ss = v0 * v0 + v1 * v1 + v2 * v2;

    __shared__ float redS[8], redQ[8];
    #pragma unroll
    for (int o = 16; o > 0; o >>= 1) {
        s  += __shfl_xor_sync(0xffffffffu, s, o);
        ss += __shfl_xor_sync(0xffffffffu, ss, o);
    }
    int warp = t >> 5, lane = t & 31;
    if (lane == 0) { redS[warp] = s; redQ[warp] = ss; }
    __syncthreads();
    float sum = 0.f, sq = 0.f;
    #pragma unroll
    for (int w = 0; w < 8; w++) { sum += redS[w]; sq += redQ[w]; }

    float mean = sum * (1.0f / D_);
    float var  = sq * (1.0f / D_) - mean * mean;
    float rs   = rsqrtf(var + 1e-5f);

    y[t]       = __float2half_rn((v0 - mean) * rs * g[t]       + b[t]);
    y[t + 256] = __float2half_rn((v1 - mean) * rs * g[t + 256] + b[t + 256]);
    y[t + 512] = __float2half_rn((v2 - mean) * rs * g[t + 512] + b[t + 512]);
}

// ---------------------------------------------------------------------------
// Batched FP16 GEMM (R13 verbatim): C[M][768] = A(half) @ W(fp32)^T + bias
// 128x128 tile, BK=32, 256 threads, warp tile 64x32; m16n8k16 fp16 mma.
// cvtOut=1 -> half output; 0 -> fp32 output.
// ---------------------------------------------------------------------------
#define GST 20
__global__ __launch_bounds__(256, 2)
void gemm3_f16(const __half* A0, const float* W0, const float* bi0, void* C0, int M0,
               const __half* A1, const float* W1, const float* bi1, void* C1, int M1,
               const __half* A2, const float* W2, const float* bi2, void* C2, int M2,
               int cvtOut) {
    const __half* A; const float* W; const float* bias; void* C; int M;
    if (blockIdx.z == 0) { A = A0; W = W0; bias = bi0; C = C0; M = M0; }
    else if (blockIdx.z == 1) { A = A1; W = W1; bias = bi1; C = C1; M = M1; }
    else { A = A2; W = W2; bias = bi2; C = C2; M = M2; }

    __shared__ unsigned As[128 * GST];
    __shared__ unsigned Ws[128 * GST];

    int t = threadIdx.x, w = t >> 5, lane = t & 31;
    int g = lane >> 2, c = lane & 3;
    int wm = w >> 2, wn = w & 3;
    int row0 = blockIdx.y * 128;
    int col0 = blockIdx.x * 128;

    float acc[4][4][4];
    #pragma unroll
    for (int i = 0; i < 4; i++)
        #pragma unroll
        for (int j = 0; j < 4; j++)
            #pragma unroll
            for (int k = 0; k < 4; k++) acc[i][j][k] = 0.f;

    for (int k0 = 0; k0 < D_; k0 += 32) {
        __syncthreads();
        // A: 128 rows x 32 halves; 512 uint4 items
        #pragma unroll
        for (int i = t; i < 512; i += 256) {
            int r = i >> 2, ch = i & 3;
            int ar = row0 + r;
            uint4 av = make_uint4(0u, 0u, 0u, 0u);
            if (ar < M) av = *(const uint4*)(A + (size_t)ar * D_ + k0 + ch * 8);
            unsigned* dst = &As[r * GST + ch * 4];
            *(uint2*)dst       = make_uint2(av.x, av.y);
            *(uint2*)(dst + 2) = make_uint2(av.z, av.w);
        }
        // W: 128 rows x 32 floats -> half2; 1024 float4 items
        #pragma unroll
        for (int i = t; i < 1024; i += 256) {
            int r = i >> 3, q = i & 7;
            float4 wv = *(const float4*)(W + (size_t)(col0 + r) * D_ + k0 + q * 4);
            *(uint2*)&Ws[r * GST + q * 2] =
                make_uint2(packh2(wv.x, wv.y), packh2(wv.z, wv.w));
        }
        __syncthreads();

        #pragma unroll
        for (int ks = 0; ks < 2; ks++) {
            int kk = ks * 8;
            unsigned a[4][4];
            #pragma unroll
            for (int mt = 0; mt < 4; mt++) {
                int base = wm * 64 + mt * 16;
                a[mt][0] = As[(base + g)     * GST + kk + c];
                a[mt][1] = As[(base + g + 8) * GST + kk + c];
                a[mt][2] = As[(base + g)     * GST + kk + 4 + c];
                a[mt][3] = As[(base + g + 8) * GST + kk + 4 + c];
            }
            #pragma unroll
            for (int nt = 0; nt < 4; nt++) {
                int n = wn * 32 + nt * 8 + g;
                unsigned b0 = Ws[n * GST + kk + c];
                unsigned b1 = Ws[n * GST + kk + 4 + c];
                #pragma unroll
                for (int mt = 0; mt < 4; mt++)
                    mma_f16(acc[mt][nt], a[mt], b0, b1);
            }
        }
    }

    #pragma unroll
    for (int mt = 0; mt < 4; mt++) {
        int rA = row0 + wm * 64 + mt * 16 + g;
        int rB = rA + 8;
        #pragma unroll
        for (int nt = 0; nt < 4; nt++) {
            int colb = col0 + wn * 32 + nt * 8 + 2 * c;
            float b0v = bias[colb], b1v = bias[colb + 1];
            float v00 = acc[mt][nt][0] + b0v, v01 = acc[mt][nt][1] + b1v;
            float v10 = acc[mt][nt][2] + b0v, v11 = acc[mt][nt][3] + b1v;
            if (cvtOut) {
                __half* Ch = (__half*)C;
                if (rA < M) *(unsigned*)&Ch[(size_t)rA * D_ + colb] = packh2(v00, v01);
                if (rB < M) *(unsigned*)&Ch[(size_t)rB * D_ + colb] = packh2(v10, v11);
            } else {
                float* Cf = (float*)C;
                if (rA < M) *(float2*)&Cf[(size_t)rA * D_ + colb] = make_float2(v00, v01);
                if (rB < M) *(float2*)&Cf[(size_t)rB * D_ + colb] = make_float2(v10, v11);
            }
        }
    }
}

// ---------------------------------------------------------------------------
// FP16 flash attention (R13 mainloop, half Oacc epilogue)
// ---------------------------------------------------------------------------
#define AQT 256
#define ASC 32
#define NCH ((S_ + ASC - 1) / ASC)
#define CHSPLIT ((NCH + NSPLIT - 1) / NSPLIT)
#define QST 36
#define KST 36
#define VST 20
#define KBUF (ASC * KST)
#define VBUF (E_ * VST)
#define ATTN_WORDS (AQT*QST + 2*KBUF + 2*VBUF + CHSPLIT*ASC)
#define ATTN_SMEM  (ATTN_WORDS * 4)

__global__ __launch_bounds__(256, 2)
void attn_f16(const __half* __restrict__ Q, const __half* __restrict__ K,
              const __half* __restrict__ V, const int* __restrict__ mask,
              __half* __restrict__ Oacc, float* __restrict__ ML) {
    extern __shared__ unsigned smu[];
    unsigned* Qs = smu;                        // [256][36]
    unsigned* Ks0 = Qs + AQT * QST;            // 2 x [32][36]
    unsigned* Vt0 = Ks0 + 2 * KBUF;            // 2 x [64 e][20]
    float* maskSm = (float*)(Vt0 + 2 * VBUF);  // [CHSPLIT*32]

    int h = blockIdx.y;
    int z = blockIdx.z;
    int row0 = blockIdx.x * AQT;
    int t = threadIdx.x, w = t >> 5, lane = t & 31;
    int g = lane >> 2, c = lane & 3;
    int wrow = w * 32;

    int chBeg = z * CHSPLIT;
    int chEnd = min(chBeg + CHSPLIT, NCH);

    #pragma unroll 4
    for (int i = t; i < AQT * 8; i += 256) {
        int r = i >> 3, part = i & 7;
        uint4 q4 = *(const uint4*)(Q + (size_t)(row0 + r) * D_ + h * E_ + part * 8);
        *(uint4*)&Qs[r * QST + part * 4] = q4;
    }
    for (int i = t; i < CHSPLIT * ASC; i += 256) {
        int gs = chBeg * ASC + i;
        maskSm[i] = (gs < S_ && mask[gs] != 0) ? 0.f : -1e30f;
    }

    auto stageK = [&](int ch, int buf) {
        unsigned* Ks = Ks0 + buf * KBUF;
        int s0 = ch * ASC;
        #pragma unroll
        for (int i = t; i < ASC * 16; i += 256) {
            int s = i >> 4, chk = i & 15;
            int gs = s0 + s;
            cp8(&Ks[s * KST + chk * 2],
                K + (size_t)gs * D_ + h * E_ + chk * 4, gs < S_);
        }
        cp_commit();
    };
    auto loadV = [&](int ch) -> uint4 {
        int gs = ch * ASC + lane;
        if (gs < S_)
            return *(const uint4*)(V + (size_t)gs * D_ + h * E_ + w * 8);
        return make_uint4(0u, 0u, 0u, 0u);
    };
    auto storeV = [&](uint4 v, int buf) {
        __half* Vth = (__half*)(Vt0 + buf * VBUF);
        const __half* hv = (const __half*)&v;
        #pragma unroll
        for (int j = 0; j < 8; j++)
            Vth[(w * 8 + j) * (VST * 2) + lane] = hv[j];
    };

    float mA[2] = {-1e30f, -1e30f}, mB[2] = {-1e30f, -1e30f};
    float lA[2] = {0.f, 0.f}, lB[2] = {0.f, 0.f};
    float acc[2][8][4];
    #pragma unroll
    for (int mt = 0; mt < 2; mt++)
        #pragma unroll
        for (int nt = 0; nt < 8; nt++)
            #pragma unroll
            for (int k = 0; k < 4; k++) acc[mt][nt][k] = 0.f;

    {
        uint4 v0 = loadV(chBeg);
        stageK(chBeg, 0);
        cp_wait<0>();
        storeV(v0, 0);
    }
    __syncthreads();

    for (int ch = chBeg; ch < chEnd; ch++) {
        int buf = (ch - chBeg) & 1;
        bool more = (ch + 1 < chEnd);
        uint4 vnext;
        if (more) {
            vnext = loadV(ch + 1);
            stageK(ch + 1, buf ^ 1);
        }

        const unsigned* Ks = Ks0 + buf * KBUF;
        const unsigned* Vt = Vt0 + buf * VBUF;
        const float* maskAdd = maskSm + (ch - chBeg) * ASC;

        float sc[2][4][4];
        #pragma unroll
        for (int mt = 0; mt < 2; mt++)
            #pragma unroll
            for (int nt = 0; nt < 4; nt++)
                #pragma unroll
                for (int k = 0; k < 4; k++) sc[mt][nt][k] = 0.f;

        #pragma unroll
        for (int ks = 0; ks < 4; ks++) {
            int kk = ks * 8;
            unsigned a[2][4];
            #pragma unroll
            for (int mt = 0; mt < 2; mt++) {
                int base = wrow + mt * 16;
                a[mt][0] = Qs[(base + g)     * QST + kk + c];
                a[mt][1] = Qs[(base + g + 8) * QST + kk + c];
                a[mt][2] = Qs[(base + g)     * QST + kk + 4 + c];
                a[mt][3] = Qs[(base + g + 8) * QST + kk + 4 + c];
            }
            #pragma unroll
            for (int nt = 0; nt < 4; nt++) {
                int n0 = nt * 8;
                unsigned b0 = Ks[(n0 + g) * KST + kk + c];
                unsigned b1 = Ks[(n0 + g) * KST + kk + 4 + c];
                mma_f16(sc[0][nt], a[0], b0, b1);
                mma_f16(sc[1][nt], a[1], b0, b1);
            }
        }

        #pragma unroll
        for (int mt = 0; mt < 2; mt++) {
            float mxA = -1e30f, mxB = -1e30f;
            #pragma unroll
            for (int nt = 0; nt < 4; nt++) {
                int j0 = nt * 8 + 2 * c;
                float ma0 = maskAdd[j0], ma1 = maskAdd[j0 + 1];
                sc[mt][nt][0] = sc[mt][nt][0] * 0.125f + ma0;
                sc[mt][nt][1] = sc[mt][nt][1] * 0.125f + ma1;
                sc[mt][nt][2] = sc[mt][nt][2] * 0.125f + ma0;
                sc[mt][nt][3] = sc[mt][nt][3] * 0.125f + ma1;
                mxA = fmaxf(mxA, fmaxf(sc[mt][nt][0], sc[mt][nt][1]));
                mxB = fmaxf(mxB, fmaxf(sc[mt][nt][2], sc[mt][nt][3]));
            }
            mxA = fmaxf(mxA, __shfl_xor_sync(0xffffffffu, mxA, 1));
            mxA = fmaxf(mxA, __shfl_xor_sync(0xffffffffu, mxA, 2));
            mxB = fmaxf(mxB, __shfl_xor_sync(0xffffffffu, mxB, 1));
            mxB = fmaxf(mxB, __shfl_xor_sync(0xffffffffu, mxB, 2));

            float mnA = fmaxf(mA[mt], mxA);
            float mnB = fmaxf(mB[mt], mxB);
            float corrA = __expf(mA[mt] - mnA);
            float corrB = __expf(mB[mt] - mnB);
            mA[mt] = mnA; mB[mt] = mnB;

            float psA = 0.f, psB = 0.f;
            #pragma unroll
            for (int nt = 0; nt < 4; nt++) {
                float p0 = __expf(sc[mt][nt][0] - mnA);
                float p1 = __expf(sc[mt][nt][1] - mnA);
                float p2 = __expf(sc[mt][nt][2] - mnB);
                float p3 = __expf(sc[mt][nt][3] - mnB);
                psA += p0 + p1; psB += p2 + p3;
                sc[mt][nt][0] = p0; sc[mt][nt][1] = p1;
                sc[mt][nt][2] = p2; sc[mt][nt][3] = p3;
            }
            psA += __shfl_xor_sync(0xffffffffu, psA, 1);
            psA += __shfl_xor_sync(0xffffffffu, psA, 2);
            psB += __shfl_xor_sync(0xffffffffu, psB, 1);
            psB += __shfl_xor_sync(0xffffffffu, psB, 2);
            lA[mt] = lA[mt] * corrA + psA;
            lB[mt] = lB[mt] * corrB + psB;
            #pragma unroll
            for (int nt = 0; nt < 8; nt++) {
                acc[mt][nt][0] *= corrA; acc[mt][nt][1] *= corrA;
                acc[mt][nt][2] *= corrB; acc[mt][nt][3] *= corrB;
            }
        }

        #pragma unroll
        for (int ks = 0; ks < 2; ks++) {
            int kk = ks * 8;
            int t0 = ks * 2, t1 = t0 + 1;
            unsigned aP[2][4];
            #pragma unroll
            for (int mt = 0; mt < 2; mt++) {
                aP[mt][0] = packh2(sc[mt][t0][0], sc[mt][t0][1]);
                aP[mt][1] = packh2(sc[mt][t0][2], sc[mt][t0][3]);
                aP[mt][2] = packh2(sc[mt][t1][0], sc[mt][t1][1]);
                aP[mt][3] = packh2(sc[mt][t1][2], sc[mt][t1][3]);
            }
            #pragma unroll
            for (int nt = 0; nt < 8; nt++) {
                int e0 = nt * 8;
                unsigned b0 = Vt[(e0 + g) * VST + kk + c];
                unsigned b1 = Vt[(e0 + g) * VST + kk + 4 + c];
                mma_f16(acc[0][nt], aP[0], b0, b1);
                mma_f16(acc[1][nt], aP[1], b0, b1);
            }
        }

        if (more) {
            cp_wait<0>();
            storeV(vnext, buf ^ 1);
        }
        __syncthreads();
    }

    // epilogue: half unnormalized acc + fp32 (m,l)
    #pragma unroll
    for (int mt = 0; mt < 2; mt++) {
        int rA = row0 + wrow + mt * 16 + g;
        int rB = rA + 8;
        __half* obase = Oacc + (size_t)z * MQ * D_;
        #pragma unroll
        for (int nt = 0; nt < 8; nt++) {
            int col = h * E_ + nt * 8 + 2 * c;
            *(unsigned*)&obase[(size_t)rA * D_ + col] = packh2(acc[mt][nt][0], acc[mt][nt][1]);
            *(unsigned*)&obase[(size_t)rB * D_ + col] = packh2(acc[mt][nt][2], acc[mt][nt][3]);
        }
        if (c == 0) {
            size_t iA = ((size_t)(z * MQ + rA) * H_ + h) * 2;
            size_t iB = ((size_t)(z * MQ + rB) * H_ + h) * 2;
            ML[iA]     = mA[mt]; ML[iA + 1] = lA[mt];
            ML[iB]     = mB[mt]; ML[iB + 1] = lB[mt];
        }
    }
}

// ---------------------------------------------------------------------------
// Split-KV combine + mean-pool (scalar, 768 blocks); half Oacc in, half out
// ---------------------------------------------------------------------------
__global__ void combine_pool_kernel(const __half* __restrict__ Oacc,
                                    const float* __restrict__ ML,
                                    __half* __restrict__ P) {
    int idx = blockIdx.x * 256 + threadIdx.x;
    if (idx >= BLn * D_) return;
    int bl = idx / D_, d = idx % D_;
    int h = d >> 6;
    float s = 0.f;
    #pragma unroll
    for (int tq = 0; tq < TQn; tq++) {
        int row = bl * TQn + tq;
        size_t i0 = ((size_t)(0 * MQ + row) * H_ + h) * 2;
        size_t i1 = ((size_t)(1 * MQ + row) * H_ + h) * 2;
        size_t i2 = ((size_t)(2 * MQ + row) * H_ + h) * 2;
        float m0 = ML[i0], l0 = ML[i0 + 1];
        float m1 = ML[i1], l1 = ML[i1 + 1];
        float m2 = ML[i2], l2 = ML[i2 + 1];
        float M = fmaxf(m0, fmaxf(m1, m2));
        float w0 = __expf(m0 - M), w1 = __expf(m1 - M), w2 = __expf(m2 - M);
        float denom = l0 * w0 + l1 * w1 + l2 * w2;
        float a0 = __half2float(Oacc[(size_t)(0 * MQ + row) * D_ + d]);
        float a1 = __half2float(Oacc[(size_t)(1 * MQ + row) * D_ + d]);
        float a2 = __half2float(Oacc[(size_t)(2 * MQ + row) * D_ + d]);
        s += (a0 * w0 + a1 * w1 + a2 * w2) / denom;
    }
    P[idx] = __float2half_rn(s * (1.0f / TQn));
}

// ---------------------------------------------------------------------------
extern "C" void kernel_launch(void* const* d_in, const int* in_sizes, int n_in,
                              void* d_out, int out_size) {
    const float* target     = (const float*)d_in[0];
    const float* key_bank   = (const float*)d_in[1];
    const float* value_bank = (const float*)d_in[2];
    const int*   bank_mask  = (const int*)  d_in[3];
    const float* Wq = (const float*)d_in[4];
    const float* bq = (const float*)d_in[5];
    const float* Wk = (const float*)d_in[6];
    const float* bk = (const float*)d_in[7];
    const float* Wv = (const float*)d_in[8];
    const float* bv = (const float*)d_in[9];
    const float* Wo = (const float*)d_in[10];
    const float* bo = (const float*)d_in[11];
    const float* gq = (const float*)d_in[12];
    const float* betaq = (const float*)d_in[13];
    const float* gkv = (const float*)d_in[14];
    const float* betakv = (const float*)d_in[15];
    float* out = (float*)d_out;

    __half *Xq, *Xk, *Xv, *Qb, *Kb, *Vb, *Oacc, *Pool;
    float *ML;
    cudaGetSymbolAddress((void**)&Xq,  g_Xq);
    cudaGetSymbolAddress((void**)&Xk,  g_Xk);
    cudaGetSymbolAddress((void**)&Xv,  g_Xv);
    cudaGetSymbolAddress((void**)&Qb,  g_Qb);
    cudaGetSymbolAddress((void**)&Kb,  g_Kb);
    cudaGetSymbolAddress((void**)&Vb,  g_Vb);
    cudaGetSymbolAddress((void**)&Oacc, g_Oacc);
    cudaGetSymbolAddress((void**)&ML,  g_ML);
    cudaGetSymbolAddress((void**)&Pool, g_Pool);

    cudaFuncSetAttribute(attn_f16,
                         cudaFuncAttributeMaxDynamicSharedMemorySize, ATTN_SMEM);

    // 1. Fused LayerNorms (half outputs)
    ln3_kernel<<<MQ + 2 * S_, 256>>>(target, Xq, gq, betaq,
                                     key_bank, value_bank, Xk, Xv, gkv, betakv);

    // 2. Q/K/V projections (fp32 weights, half outputs) — R13 gemm
    gemm3_f16<<<dim3(D_ / 128, 16, 3), 256>>>(
        Xq, Wq, bq, Qb, MQ,
        Xk, Wk, bk, Kb, S_,
        Xv, Wv, bv, Vb, S_, 1);

    // 3. Attention: fp16 mma, split-KV x3, one wave; half Oacc
    attn_f16<<<dim3(MQ / AQT, H_, NSPLIT), 256, ATTN_SMEM>>>(
        Qb, Kb, Vb, bank_mask, Oacc, ML);

    // 4. Combine + mean-pool (half in/out)
    combine_pool_kernel<<<(BLn * D_ + 255) / 256, 256>>>(Oacc, ML, Pool);

    // 5. Output projection (fp32 out)
    gemm3_f16<<<dim3(D_ / 128, 2, 1), 256>>>(
        Pool, Wo, bo, out, BLn,
        Pool, Wo, bo, out, BLn,
        Pool, Wo, bo, out, BLn, 0);
}

// round 16
// speedup vs baseline: 1.0453x; 1.0174x over previous
#include <cuda_runtime.h>
#include <cuda_fp16.h>
#include <math.h>

// Problem constants
#define D_  768
#define H_  12
#define E_  64
#define S_  2000
#define MQ  2048
#define BLn 256
#define TQn 8
#define NSPLIT 3
#define SCL (0.125f * 1.4426950408889634f)   /* 1/sqrt(64) * log2(e) */

// Scratch (device globals)
__device__ __half g_Xq[MQ * D_];
__device__ __half g_Xk[S_ * D_];
__device__ __half g_Xv[S_ * D_];
__device__ __half g_Qb[MQ * D_];
__device__ __half g_Kb[S_ * D_];
__device__ __half g_Vb[S_ * D_];
__device__ __half g_Oacc[NSPLIT * MQ * D_];
__device__ float  g_ML[NSPLIT * MQ * H_ * 2];   // (m in log2 domain, l)
__device__ __half g_Pool[BLn * D_];

// ---------------------------------------------------------------------------
// helpers
// ---------------------------------------------------------------------------
__device__ __forceinline__ void mma_f16(float* d, const unsigned* a,
                                        unsigned b0, unsigned b1) {
    asm volatile(
        "mma.sync.aligned.m16n8k16.row.col.f32.f16.f16.f32 "
        "{%0,%1,%2,%3},{%4,%5,%6,%7},{%8,%9},{%0,%1,%2,%3};\n"
        : "+f"(d[0]), "+f"(d[1]), "+f"(d[2]), "+f"(d[3])
        : "r"(a[0]), "r"(a[1]), "r"(a[2]), "r"(a[3]), "r"(b0), "r"(b1));
}

__device__ __forceinline__ unsigned packh2(float x, float y) {
    __half2 h = __floats2half2_rn(x, y);
    return *reinterpret_cast<unsigned*>(&h);
}

__device__ __forceinline__ void cp8(unsigned* dst_smem, const void* src, bool valid) {
    unsigned d = (unsigned)__cvta_generic_to_shared(dst_smem);
    int sz = valid ? 8 : 0;
    asm volatile("cp.async.ca.shared.global [%0], [%1], 8, %2;\n"
                 :: "r"(d), "l"(src), "r"(sz));
}
__device__ __forceinline__ void cp_commit() {
    asm volatile("cp.async.commit_group;\n");
}
template <int N>
__device__ __forceinline__ void cp_wait() {
    asm volatile("cp.async.wait_group %0;\n" :: "n"(N));
}

// ---------------------------------------------------------------------------
// Fused LayerNorm -> half outputs
// ---------------------------------------------------------------------------
__global__ void ln3_kernel(const float* __restrict__ tgt, __half* __restrict__ Xq,
                           const float* __restrict__ gq, const float* __restrict__ bq_,
                           const float* __restrict__ key, const float* __restrict__ val,
                           __half* __restrict__ Xk, __half* __restrict__ Xv,
                           const float* __restrict__ gkv, const float* __restrict__ bkv) {
    int row = blockIdx.x;
    const float *x, *g, *b;
    __half* y;
    if (row < MQ) {
        x = tgt + (size_t)row * D_; y = Xq + (size_t)row * D_; g = gq; b = bq_;
    } else if (row < MQ + S_) {
        int r = row - MQ;
        x = key + (size_t)r * D_; y = Xk + (size_t)r * D_; g = gkv; b = bkv;
    } else {
        int r = row - MQ - S_;
        x = val + (size_t)r * D_; y = Xv + (size_t)r * D_; g = gkv; b = bkv;
    }

    int t = threadIdx.x;
    float v0 = x[t], v1 = x[t + 256], v2 = x[t + 512];
    float s  = v0 + v1 + v2;
    float ss = v0 * v0 + v1 * v1 + v2 * v2;

    __shared__ float redS[8], redQ[8];
    #pragma unroll
    for (int o = 16; o > 0; o >>= 1) {
        s  += __shfl_xor_sync(0xffffffffu, s, o);
        ss += __shfl_xor_sync(0xffffffffu, ss, o);
    }
    int warp = t >> 5, lane = t & 31;
    if (lane == 0) { redS[warp] = s; redQ[warp] = ss; }
    __syncthreads();
    float sum = 0.f, sq = 0.f;
    #pragma unroll
    for (int w = 0; w < 8; w++) { sum += redS[w]; sq += redQ[w]; }

    float mean = sum * (1.0f / D_);
    float var  = sq * (1.0f / D_) - mean * mean;
    float rs   = rsqrtf(var + 1e-5f);

    y[t]       = __float2half_rn((v0 - mean) * rs * g[t]       + b[t]);
    y[t + 256] = __float2half_rn((v1 - mean) * rs * g[t + 256] + b[t + 256]);
    y[t + 512] = __float2half_rn((v2 - mean) * rs * g[t + 512] + b[t + 512]);
}

// ---------------------------------------------------------------------------
// Batched FP16 GEMM (R13 verbatim)
// ---------------------------------------------------------------------------
#define GST 20
__global__ __launch_bounds__(256, 2)
void gemm3_f16(const __half* A0, const float* W0, const float* bi0, void* C0, int M0,
               const __half* A1, const float* W1, const float* bi1, void* C1, int M1,
               const __half* A2, const float* W2, const float* bi2, void* C2, int M2,
               int cvtOut) {
    const __half* A; const float* W; const float* bias; void* C; int M;
    if (blockIdx.z == 0) { A = A0; W = W0; bias = bi0; C = C0; M = M0; }
    else if (blockIdx.z == 1) { A = A1; W = W1; bias = bi1; C = C1; M = M1; }
    else { A = A2; W = W2; bias = bi2; C = C2; M = M2; }

    __shared__ unsigned As[128 * GST];
    __shared__ unsigned Ws[128 * GST];

    int t = threadIdx.x, w = t >> 5, lane = t & 31;
    int g = lane >> 2, c = lane & 3;
    int wm = w >> 2, wn = w & 3;
    int row0 = blockIdx.y * 128;
    int col0 = blockIdx.x * 128;

    float acc[4][4][4];
    #pragma unroll
    for (int i = 0; i < 4; i++)
        #pragma unroll
        for (int j = 0; j < 4; j++)
            #pragma unroll
            for (int k = 0; k < 4; k++) acc[i][j][k] = 0.f;

    for (int k0 = 0; k0 < D_; k0 += 32) {
        __syncthreads();
        #pragma unroll
        for (int i = t; i < 512; i += 256) {
            int r = i >> 2, ch = i & 3;
            int ar = row0 + r;
            uint4 av = make_uint4(0u, 0u, 0u, 0u);
            if (ar < M) av = *(const uint4*)(A + (size_t)ar * D_ + k0 + ch * 8);
            unsigned* dst = &As[r * GST + ch * 4];
            *(uint2*)dst       = make_uint2(av.x, av.y);
            *(uint2*)(dst + 2) = make_uint2(av.z, av.w);
        }
        #pragma unroll
        for (int i = t; i < 1024; i += 256) {
            int r = i >> 3, q = i & 7;
            float4 wv = *(const float4*)(W + (size_t)(col0 + r) * D_ + k0 + q * 4);
            *(uint2*)&Ws[r * GST + q * 2] =
                make_uint2(packh2(wv.x, wv.y), packh2(wv.z, wv.w));
        }
        __syncthreads();

        #pragma unroll
        for (int ks = 0; ks < 2; ks++) {
            int kk = ks * 8;
            unsigned a[4][4];
            #pragma unroll
            for (int mt = 0; mt < 4; mt++) {
                int base = wm * 64 + mt * 16;
                a[mt][0] = As[(base + g)     * GST + kk + c];
                a[mt][1] = As[(base + g + 8) * GST + kk + c];
                a[mt][2] = As[(base + g)     * GST + kk + 4 + c];
                a[mt][3] = As[(base + g + 8) * GST + kk + 4 + c];
            }
            #pragma unroll
            for (int nt = 0; nt < 4; nt++) {
                int n = wn * 32 + nt * 8 + g;
                unsigned b0 = Ws[n * GST + kk + c];
                unsigned b1 = Ws[n * GST + kk + 4 + c];
                #pragma unroll
                for (int mt = 0; mt < 4; mt++)
                    mma_f16(acc[mt][nt], a[mt], b0, b1);
            }
        }
    }

    #pragma unroll
    for (int mt = 0; mt < 4; mt++) {
        int rA = row0 + wm * 64 + mt * 16 + g;
        int rB = rA + 8;
        #pragma unroll
        for (int nt = 0; nt < 4; nt++) {
            int colb = col0 + wn * 32 + nt * 8 + 2 * c;
            float b0v = bias[colb], b1v = bias[colb + 1];
            float v00 = acc[mt][nt][0] + b0v, v01 = acc[mt][nt][1] + b1v;
            float v10 = acc[mt][nt][2] + b0v, v11 = acc[mt][nt][3] + b1v;
            if (cvtOut) {
                __half* Ch = (__half*)C;
                if (rA < M) *(unsigned*)&Ch[(size_t)rA * D_ + colb] = packh2(v00, v01);
                if (rB < M) *(unsigned*)&Ch[(size_t)rB * D_ + colb] = packh2(v10, v11);
            } else {
                float* Cf = (float*)C;
                if (rA < M) *(float2*)&Cf[(size_t)rA * D_ + colb] = make_float2(v00, v01);
                if (rB < M) *(float2*)&Cf[(size_t)rB * D_ + colb] = make_float2(v10, v11);
            }
        }
    }
}

// ---------------------------------------------------------------------------
// FP16 flash attention — exp2-domain softmax (m, scores in log2 units)
// ---------------------------------------------------------------------------
#define AQT 256
#define ASC 32
#define NCH ((S_ + ASC - 1) / ASC)
#define CHSPLIT ((NCH + NSPLIT - 1) / NSPLIT)
#define QST 36
#define KST 36
#define VST 20
#define KBUF (ASC * KST)
#define VBUF (E_ * VST)
#define ATTN_WORDS (AQT*QST + 2*KBUF + 2*VBUF + CHSPLIT*ASC)
#define ATTN_SMEM  (ATTN_WORDS * 4)

__global__ __launch_bounds__(256, 2)
void attn_f16(const __half* __restrict__ Q, const __half* __restrict__ K,
              const __half* __restrict__ V, const int* __restrict__ mask,
              __half* __restrict__ Oacc, float* __restrict__ ML) {
    extern __shared__ unsigned smu[];
    unsigned* Qs = smu;                        // [256][36]
    unsigned* Ks0 = Qs + AQT * QST;            // 2 x [32][36]
    unsigned* Vt0 = Ks0 + 2 * KBUF;            // 2 x [64 e][20]
    float* maskSm = (float*)(Vt0 + 2 * VBUF);  // [CHSPLIT*32]

    int h = blockIdx.y;
    int z = blockIdx.z;
    int row0 = blockIdx.x * AQT;
    int t = threadIdx.x, w = t >> 5, lane = t & 31;
    int g = lane >> 2, c = lane & 3;
    int wrow = w * 32;

    int chBeg = z * CHSPLIT;
    int chEnd = min(chBeg + CHSPLIT, NCH);

    #pragma unroll 4
    for (int i = t; i < AQT * 8; i += 256) {
        int r = i >> 3, part = i & 7;
        uint4 q4 = *(const uint4*)(Q + (size_t)(row0 + r) * D_ + h * E_ + part * 8);
        *(uint4*)&Qs[r * QST + part * 4] = q4;
    }
    for (int i = t; i < CHSPLIT * ASC; i += 256) {
        int gs = chBeg * ASC + i;
        maskSm[i] = (gs < S_ && mask[gs] != 0) ? 0.f : -1e30f;
    }

    auto stageK = [&](int ch, int buf) {
        unsigned* Ks = Ks0 + buf * KBUF;
        int s0 = ch * ASC;
        #pragma unroll
        for (int i = t; i < ASC * 16; i += 256) {
            int s = i >> 4, chk = i & 15;
            int gs = s0 + s;
            cp8(&Ks[s * KST + chk * 2],
                K + (size_t)gs * D_ + h * E_ + chk * 4, gs < S_);
        }
        cp_commit();
    };
    auto loadV = [&](int ch) -> uint4 {
        int gs = ch * ASC + lane;
        if (gs < S_)
            return *(const uint4*)(V + (size_t)gs * D_ + h * E_ + w * 8);
        return make_uint4(0u, 0u, 0u, 0u);
    };
    auto storeV = [&](uint4 v, int buf) {
        __half* Vth = (__half*)(Vt0 + buf * VBUF);
        const __half* hv = (const __half*)&v;
        #pragma unroll
        for (int j = 0; j < 8; j++)
            Vth[(w * 8 + j) * (VST * 2) + lane] = hv[j];
    };

    float mA[2] = {-1e30f, -1e30f}, mB[2] = {-1e30f, -1e30f};
    float lA[2] = {0.f, 0.f}, lB[2] = {0.f, 0.f};
    float acc[2][8][4];
    #pragma unroll
    for (int mt = 0; mt < 2; mt++)
        #pragma unroll
        for (int nt = 0; nt < 8; nt++)
            #pragma unroll
            for (int k = 0; k < 4; k++) acc[mt][nt][k] = 0.f;

    {
        uint4 v0 = loadV(chBeg);
        stageK(chBeg, 0);
        cp_wait<0>();
        storeV(v0, 0);
    }
    __syncthreads();

    for (int ch = chBeg; ch < chEnd; ch++) {
        int buf = (ch - chBeg) & 1;
        bool more = (ch + 1 < chEnd);
        uint4 vnext;
        if (more) {
            vnext = loadV(ch + 1);
            stageK(ch + 1, buf ^ 1);
        }

        const unsigned* Ks = Ks0 + buf * KBUF;
        const unsigned* Vt = Vt0 + buf * VBUF;
        const float* maskAdd = maskSm + (ch - chBeg) * ASC;

        float sc[2][4][4];
        #pragma unroll
        for (int mt = 0; mt < 2; mt++)
            #pragma unroll
            for (int nt = 0; nt < 4; nt++)
                #pragma unroll
                for (int k = 0; k < 4; k++) sc[mt][nt][k] = 0.f;

        #pragma unroll
        for (int ks = 0; ks < 4; ks++) {
            int kk = ks * 8;
            unsigned a[2][4];
            #pragma unroll
            for (int mt = 0; mt < 2; mt++) {
                int base = wrow + mt * 16;
                a[mt][0] = Qs[(base + g)     * QST + kk + c];
                a[mt][1] = Qs[(base + g + 8) * QST + kk + c];
                a[mt][2] = Qs[(base + g)     * QST + kk + 4 + c];
                a[mt][3] = Qs[(base + g + 8) * QST + kk + 4 + c];
            }
            #pragma unroll
            for (int nt = 0; nt < 4; nt++) {
                int n0 = nt * 8;
                unsigned b0 = Ks[(n0 + g) * KST + kk + c];
                unsigned b1 = Ks[(n0 + g) * KST + kk + 4 + c];
                mma_f16(sc[0][nt], a[0], b0, b1);
                mma_f16(sc[1][nt], a[1], b0, b1);
            }
        }

        // ---- online softmax in log2 domain ----
        #pragma unroll
        for (int mt = 0; mt < 2; mt++) {
            float mxA = -1e30f, mxB = -1e30f;
            #pragma unroll
            for (int nt = 0; nt < 4; nt++) {
                int j0 = nt * 8 + 2 * c;
                float ma0 = maskAdd[j0], ma1 = maskAdd[j0 + 1];
                sc[mt][nt][0] = sc[mt][nt][0] * SCL + ma0;
                sc[mt][nt][1] = sc[mt][nt][1] * SCL + ma1;
                sc[mt][nt][2] = sc[mt][nt][2] * SCL + ma0;
                sc[mt][nt][3] = sc[mt][nt][3] * SCL + ma1;
                mxA = fmaxf(mxA, fmaxf(sc[mt][nt][0], sc[mt][nt][1]));
                mxB = fmaxf(mxB, fmaxf(sc[mt][nt][2], sc[mt][nt][3]));
            }
            mxA = fmaxf(mxA, __shfl_xor_sync(0xffffffffu, mxA, 1));
            mxA = fmaxf(mxA, __shfl_xor_sync(0xffffffffu, mxA, 2));
            mxB = fmaxf(mxB, __shfl_xor_sync(0xffffffffu, mxB, 1));
            mxB = fmaxf(mxB, __shfl_xor_sync(0xffffffffu, mxB, 2));

            float mnA = fmaxf(mA[mt], mxA);
            float mnB = fmaxf(mB[mt], mxB);
            float corrA = exp2f(mA[mt] - mnA);
            float corrB = exp2f(mB[mt] - mnB);
            mA[mt] = mnA; mB[mt] = mnB;

            float psA = 0.f, psB = 0.f;
            #pragma unroll
            for (int nt = 0; nt < 4; nt++) {
                float p0 = exp2f(sc[mt][nt][0] - mnA);
                float p1 = exp2f(sc[mt][nt][1] - mnA);
                float p2 = exp2f(sc[mt][nt][2] - mnB);
                float p3 = exp2f(sc[mt][nt][3] - mnB);
                psA += p0 + p1; psB += p2 + p3;
                sc[mt][nt][0] = p0; sc[mt][nt][1] = p1;
                sc[mt][nt][2] = p2; sc[mt][nt][3] = p3;
            }
            psA += __shfl_xor_sync(0xffffffffu, psA, 1);
            psA += __shfl_xor_sync(0xffffffffu, psA, 2);
            psB += __shfl_xor_sync(0xffffffffu, psB, 1);
            psB += __shfl_xor_sync(0xffffffffu, psB, 2);
            lA[mt] = lA[mt] * corrA + psA;
            lB[mt] = lB[mt] * corrB + psB;
            #pragma unroll
            for (int nt = 0; nt < 8; nt++) {
                acc[mt][nt][0] *= corrA; acc[mt][nt][1] *= corrA;
                acc[mt][nt][2] *= corrB; acc[mt][nt][3] *= corrB;
            }
        }

        #pragma unroll
        for (int ks = 0; ks < 2; ks++) {
            int kk = ks * 8;
            int t0 = ks * 2, t1 = t0 + 1;
            unsigned aP[2][4];
            #pragma unroll
            for (int mt = 0; mt < 2; mt++) {
                aP[mt][0] = packh2(sc[mt][t0][0], sc[mt][t0][1]);
                aP[mt][1] = packh2(sc[mt][t0][2], sc[mt][t0][3]);
                aP[mt][2] = packh2(sc[mt][t1][0], sc[mt][t1][1]);
                aP[mt][3] = packh2(sc[mt][t1][2], sc[mt][t1][3]);
            }
            #pragma unroll
            for (int nt = 0; nt < 8; nt++) {
                int e0 = nt * 8;
                unsigned b0 = Vt[(e0 + g) * VST + kk + c];
                unsigned b1 = Vt[(e0 + g) * VST + kk + 4 + c];
                mma_f16(acc[0][nt], aP[0], b0, b1);
                mma_f16(acc[1][nt], aP[1], b0, b1);
            }
        }

        if (more) {
            cp_wait<0>();
            storeV(vnext, buf ^ 1);
        }
        __syncthreads();
    }

    // epilogue: half unnormalized acc + fp32 (m[log2], l)
    #pragma unroll
    for (int mt = 0; mt < 2; mt++) {
        int rA = row0 + wrow + mt * 16 + g;
        int rB = rA + 8;
        __half* obase = Oacc + (size_t)z * MQ * D_;
        #pragma unroll
        for (int nt = 0; nt < 8; nt++) {
            int col = h * E_ + nt * 8 + 2 * c;
            *(unsigned*)&obase[(size_t)rA * D_ + col] = packh2(acc[mt][nt][0], acc[mt][nt][1]);
            *(unsigned*)&obase[(size_t)rB * D_ + col] = packh2(acc[mt][nt][2], acc[mt][nt][3]);
        }
        if (c == 0) {
            size_t iA = ((size_t)(z * MQ + rA) * H_ + h) * 2;
            size_t iB = ((size_t)(z * MQ + rB) * H_ + h) * 2;
            ML[iA]     = mA[mt]; ML[iA + 1] = lA[mt];
            ML[iB]     = mB[mt]; ML[iB + 1] = lB[mt];
        }
    }
}

// ---------------------------------------------------------------------------
// Split-KV combine + mean-pool: one block per bl row; 96 threads precompute
// the (tq,h) normalized weight triples in smem; 256 threads emit 3 d each.
// m values are in log2 domain -> exp2f.
// ---------------------------------------------------------------------------
__global__ void combine_pool_kernel(const __half* __restrict__ Oacc,
                                    const float* __restrict__ ML,
                                    __half* __restrict__ P) {
    __shared__ float wS[TQn * H_ * 3];   // [tq*H+h][3]
    int bl = blockIdx.x;
    int t = threadIdx.x;

    if (t < TQn * H_) {
        int tq = t / H_, h = t % H_;
        int row = bl * TQn + tq;
        size_t i0 = ((size_t)(0 * MQ + row) * H_ + h) * 2;
        size_t i1 = ((size_t)(1 * MQ + row) * H_ + h) * 2;
        size_t i2 = ((size_t)(2 * MQ + row) * H_ + h) * 2;
        float m0 = ML[i0], l0 = ML[i0 + 1];
        float m1 = ML[i1], l1 = ML[i1 + 1];
        float m2 = ML[i2], l2 = ML[i2 + 1];
        float M = fmaxf(m0, fmaxf(m1, m2));
        float w0 = exp2f(m0 - M), w1 = exp2f(m1 - M), w2 = exp2f(m2 - M);
        float inv = 1.0f / (l0 * w0 + l1 * w1 + l2 * w2);
        wS[t * 3 + 0] = w0 * inv * (1.0f / TQn);
        wS[t * 3 + 1] = w1 * inv * (1.0f / TQn);
        wS[t * 3 + 2] = w2 * inv * (1.0f / TQn);
    }
    __syncthreads();

    #pragma unroll
    for (int j = 0; j < 3; j++) {
        int d = t + j * 256;
        int h = d >> 6;
        float s = 0.f;
        #pragma unroll
        for (int tq = 0; tq < TQn; tq++) {
            int row = bl * TQn + tq;
            const float* wp = &wS[(tq * H_ + h) * 3];
            float a0 = __half2float(Oacc[(size_t)(0 * MQ + row) * D_ + d]);
            float a1 = __half2float(Oacc[(size_t)(1 * MQ + row) * D_ + d]);
            float a2 = __half2float(Oacc[(size_t)(2 * MQ + row) * D_ + d]);
            s += a0 * wp[0] + a1 * wp[1] + a2 * wp[2];
        }
        P[(size_t)bl * D_ + d] = __float2half_rn(s);
    }
}

// ---------------------------------------------------------------------------
extern "C" void kernel_launch(void* const* d_in, const int* in_sizes, int n_in,
                              void* d_out, int out_size) {
    const float* target     = (const float*)d_in[0];
    const float* key_bank   = (const float*)d_in[1];
    const float* value_bank = (const float*)d_in[2];
    const int*   bank_mask  = (const int*)  d_in[3];
    const float* Wq = (const float*)d_in[4];
    const float* bq = (const float*)d_in[5];
    const float* Wk = (const float*)d_in[6];
    const float* bk = (const float*)d_in[7];
    const float* Wv = (const float*)d_in[8];
    const float* bv = (const float*)d_in[9];
    const float* Wo = (const float*)d_in[10];
    const float* bo = (const float*)d_in[11];
    const float* gq = (const float*)d_in[12];
    const float* betaq = (const float*)d_in[13];
    const float* gkv = (const float*)d_in[14];
    const float* betakv = (const float*)d_in[15];
    float* out = (float*)d_out;

    __half *Xq, *Xk, *Xv, *Qb, *Kb, *Vb, *Oacc, *Pool;
    float *ML;
    cudaGetSymbolAddress((void**)&Xq,  g_Xq);
    cudaGetSymbolAddress((void**)&Xk,  g_Xk);
    cudaGetSymbolAddress((void**)&Xv,  g_Xv);
    cudaGetSymbolAddress((void**)&Qb,  g_Qb);
    cudaGetSymbolAddress((void**)&Kb,  g_Kb);
    cudaGetSymbolAddress((void**)&Vb,  g_Vb);
    cudaGetSymbolAddress((void**)&Oacc, g_Oacc);
    cudaGetSymbolAddress((void**)&ML,  g_ML);
    cudaGetSymbolAddress((void**)&Pool, g_Pool);

    cudaFuncSetAttribute(attn_f16,
                         cudaFuncAttributeMaxDynamicSharedMemorySize, ATTN_SMEM);

    // 1. Fused LayerNorms (half outputs)
    ln3_kernel<<<MQ + 2 * S_, 256>>>(target, Xq, gq, betaq,
                                     key_bank, value_bank, Xk, Xv, gkv, betakv);

    // 2. Q/K/V projections (fp32 weights, half outputs)
    gemm3_f16<<<dim3(D_ / 128, 16, 3), 256>>>(
        Xq, Wq, bq, Qb, MQ,
        Xk, Wk, bk, Kb, S_,
        Xv, Wv, bv, Vb, S_, 1);

    // 3. Attention: fp16 mma, exp2 softmax, split-KV x3, one wave
    attn_f16<<<dim3(MQ / AQT, H_, NSPLIT), 256, ATTN_SMEM>>>(
        Qb, Kb, Vb, bank_mask, Oacc, ML);

    // 4. Combine + mean-pool (block-shared weights)
    combine_pool_kernel<<<BLn, 256>>>(Oacc, ML, Pool);

    // 5. Output projection (fp32 out)
    gemm3_f16<<<dim3(D_ / 128, 2, 1), 256>>>(
        Pool, Wo, bo, out, BLn,
        Pool, Wo, bo, out, BLn,
        Pool, Wo, bo, out, BLn, 0);
}

// round 17
// speedup vs baseline: 1.0720x; 1.0255x over previous
#include <cuda_runtime.h>
#include <cuda_fp16.h>
#include <math.h>

// Problem constants
#define D_  768
#define H_  12
#define E_  64
#define S_  2000
#define MQ  2048
#define BLn 256
#define TQn 8
#define NSPLIT 3
#define SCL (0.125f * 1.4426950408889634f)   /* 1/sqrt(64) * log2(e) */

// Scratch (device globals)
__device__ __half g_Xq[MQ * D_];
__device__ __half g_Xk[S_ * D_];
__device__ __half g_Xv[S_ * D_];
__device__ __half g_Qb[MQ * D_];
__device__ __half g_Kb[S_ * D_];
__device__ __half g_Vb[S_ * D_];
__device__ __half g_Oacc[NSPLIT * MQ * D_];
__device__ float  g_ML[NSPLIT * MQ * H_ * 2];   // (m in log2 domain, l)
__device__ __half g_Pool[BLn * D_];

// ---------------------------------------------------------------------------
// helpers
// ---------------------------------------------------------------------------
__device__ __forceinline__ void mma_f16(float* d, const unsigned* a,
                                        unsigned b0, unsigned b1) {
    asm volatile(
        "mma.sync.aligned.m16n8k16.row.col.f32.f16.f16.f32 "
        "{%0,%1,%2,%3},{%4,%5,%6,%7},{%8,%9},{%0,%1,%2,%3};\n"
        : "+f"(d[0]), "+f"(d[1]), "+f"(d[2]), "+f"(d[3])
        : "r"(a[0]), "r"(a[1]), "r"(a[2]), "r"(a[3]), "r"(b0), "r"(b1));
}

__device__ __forceinline__ unsigned packh2(float x, float y) {
    __half2 h = __floats2half2_rn(x, y);
    return *reinterpret_cast<unsigned*>(&h);
}

__device__ __forceinline__ void cp8(unsigned* dst_smem, const void* src, bool valid) {
    unsigned d = (unsigned)__cvta_generic_to_shared(dst_smem);
    int sz = valid ? 8 : 0;
    asm volatile("cp.async.ca.shared.global [%0], [%1], 8, %2;\n"
                 :: "r"(d), "l"(src), "r"(sz));
}
__device__ __forceinline__ void cp_commit() {
    asm volatile("cp.async.commit_group;\n");
}
template <int N>
__device__ __forceinline__ void cp_wait() {
    asm volatile("cp.async.wait_group %0;\n" :: "n"(N));
}

// ---------------------------------------------------------------------------
// Fused LayerNorm -> half outputs
// ---------------------------------------------------------------------------
__global__ void ln3_kernel(const float* __restrict__ tgt, __half* __restrict__ Xq,
                           const float* __restrict__ gq, const float* __restrict__ bq_,
                           const float* __restrict__ key, const float* __restrict__ val,
                           __half* __restrict__ Xk, __half* __restrict__ Xv,
                           const float* __restrict__ gkv, const float* __restrict__ bkv) {
    int row = blockIdx.x;
    const float *x, *g, *b;
    __half* y;
    if (row < MQ) {
        x = tgt + (size_t)row * D_; y = Xq + (size_t)row * D_; g = gq; b = bq_;
    } else if (row < MQ + S_) {
        int r = row - MQ;
        x = key + (size_t)r * D_; y = Xk + (size_t)r * D_; g = gkv; b = bkv;
    } else {
        int r = row - MQ - S_;
        x = val + (size_t)r * D_; y = Xv + (size_t)r * D_; g = gkv; b = bkv;
    }

    int t = threadIdx.x;
    float v0 = x[t], v1 = x[t + 256], v2 = x[t + 512];
    float s  = v0 + v1 + v2;
    float ss = v0 * v0 + v1 * v1 + v2 * v2;

    __shared__ float redS[8], redQ[8];
    #pragma unroll
    for (int o = 16; o > 0; o >>= 1) {
        s  += __shfl_xor_sync(0xffffffffu, s, o);
        ss += __shfl_xor_sync(0xffffffffu, ss, o);
    }
    int warp = t >> 5, lane = t & 31;
    if (lane == 0) { redS[warp] = s; redQ[warp] = ss; }
    __syncthreads();
    float sum = 0.f, sq = 0.f;
    #pragma unroll
    for (int w = 0; w < 8; w++) { sum += redS[w]; sq += redQ[w]; }

    float mean = sum * (1.0f / D_);
    float var  = sq * (1.0f / D_) - mean * mean;
    float rs   = rsqrtf(var + 1e-5f);

    y[t]       = __float2half_rn((v0 - mean) * rs * g[t]       + b[t]);
    y[t + 256] = __float2half_rn((v1 - mean) * rs * g[t + 256] + b[t + 256]);
    y[t + 512] = __float2half_rn((v2 - mean) * rs * g[t + 512] + b[t + 512]);
}

// ---------------------------------------------------------------------------
// Batched FP16 GEMM (R13 verbatim)
// ---------------------------------------------------------------------------
#define GST 20
__global__ __launch_bounds__(256, 2)
void gemm3_f16(const __half* A0, const float* W0, const float* bi0, void* C0, int M0,
               const __half* A1, const float* W1, const float* bi1, void* C1, int M1,
               const __half* A2, const float* W2, const float* bi2, void* C2, int M2,
               int cvtOut) {
    const __half* A; const float* W; const float* bias; void* C; int M;
    if (blockIdx.z == 0) { A = A0; W = W0; bias = bi0; C = C0; M = M0; }
    else if (blockIdx.z == 1) { A = A1; W = W1; bias = bi1; C = C1; M = M1; }
    else { A = A2; W = W2; bias = bi2; C = C2; M = M2; }

    __shared__ unsigned As[128 * GST];
    __shared__ unsigned Ws[128 * GST];

    int t = threadIdx.x, w = t >> 5, lane = t & 31;
    int g = lane >> 2, c = lane & 3;
    int wm = w >> 2, wn = w & 3;
    int row0 = blockIdx.y * 128;
    int col0 = blockIdx.x * 128;

    float acc[4][4][4];
    #pragma unroll
    for (int i = 0; i < 4; i++)
        #pragma unroll
        for (int j = 0; j < 4; j++)
            #pragma unroll
            for (int k = 0; k < 4; k++) acc[i][j][k] = 0.f;

    for (int k0 = 0; k0 < D_; k0 += 32) {
        __syncthreads();
        #pragma unroll
        for (int i = t; i < 512; i += 256) {
            int r = i >> 2, ch = i & 3;
            int ar = row0 + r;
            uint4 av = make_uint4(0u, 0u, 0u, 0u);
            if (ar < M) av = *(const uint4*)(A + (size_t)ar * D_ + k0 + ch * 8);
            unsigned* dst = &As[r * GST + ch * 4];
            *(uint2*)dst       = make_uint2(av.x, av.y);
            *(uint2*)(dst + 2) = make_uint2(av.z, av.w);
        }
        #pragma unroll
        for (int i = t; i < 1024; i += 256) {
            int r = i >> 3, q = i & 7;
            float4 wv = *(const float4*)(W + (size_t)(col0 + r) * D_ + k0 + q * 4);
            *(uint2*)&Ws[r * GST + q * 2] =
                make_uint2(packh2(wv.x, wv.y), packh2(wv.z, wv.w));
        }
        __syncthreads();

        #pragma unroll
        for (int ks = 0; ks < 2; ks++) {
            int kk = ks * 8;
            unsigned a[4][4];
            #pragma unroll
            for (int mt = 0; mt < 4; mt++) {
                int base = wm * 64 + mt * 16;
                a[mt][0] = As[(base + g)     * GST + kk + c];
                a[mt][1] = As[(base + g + 8) * GST + kk + c];
                a[mt][2] = As[(base + g)     * GST + kk + 4 + c];
                a[mt][3] = As[(base + g + 8) * GST + kk + 4 + c];
            }
            #pragma unroll
            for (int nt = 0; nt < 4; nt++) {
                int n = wn * 32 + nt * 8 + g;
                unsigned b0 = Ws[n * GST + kk + c];
                unsigned b1 = Ws[n * GST + kk + 4 + c];
                #pragma unroll
                for (int mt = 0; mt < 4; mt++)
                    mma_f16(acc[mt][nt], a[mt], b0, b1);
            }
        }
    }

    #pragma unroll
    for (int mt = 0; mt < 4; mt++) {
        int rA = row0 + wm * 64 + mt * 16 + g;
        int rB = rA + 8;
        #pragma unroll
        for (int nt = 0; nt < 4; nt++) {
            int colb = col0 + wn * 32 + nt * 8 + 2 * c;
            float b0v = bias[colb], b1v = bias[colb + 1];
            float v00 = acc[mt][nt][0] + b0v, v01 = acc[mt][nt][1] + b1v;
            float v10 = acc[mt][nt][2] + b0v, v11 = acc[mt][nt][3] + b1v;
            if (cvtOut) {
                __half* Ch = (__half*)C;
                if (rA < M) *(unsigned*)&Ch[(size_t)rA * D_ + colb] = packh2(v00, v01);
                if (rB < M) *(unsigned*)&Ch[(size_t)rB * D_ + colb] = packh2(v10, v11);
            } else {
                float* Cf = (float*)C;
                if (rA < M) *(float2*)&Cf[(size_t)rA * D_ + colb] = make_float2(v00, v01);
                if (rB < M) *(float2*)&Cf[(size_t)rB * D_ + colb] = make_float2(v10, v11);
            }
        }
    }
}

// ---------------------------------------------------------------------------
// FP16 flash attention — exp2-domain softmax (R16 verbatim)
// ---------------------------------------------------------------------------
#define AQT 256
#define ASC 32
#define NCH ((S_ + ASC - 1) / ASC)
#define CHSPLIT ((NCH + NSPLIT - 1) / NSPLIT)
#define QST 36
#define KST 36
#define VST 20
#define KBUF (ASC * KST)
#define VBUF (E_ * VST)
#define ATTN_WORDS (AQT*QST + 2*KBUF + 2*VBUF + CHSPLIT*ASC)
#define ATTN_SMEM  (ATTN_WORDS * 4)

__global__ __launch_bounds__(256, 2)
void attn_f16(const __half* __restrict__ Q, const __half* __restrict__ K,
              const __half* __restrict__ V, const int* __restrict__ mask,
              __half* __restrict__ Oacc, float* __restrict__ ML) {
    extern __shared__ unsigned smu[];
    unsigned* Qs = smu;                        // [256][36]
    unsigned* Ks0 = Qs + AQT * QST;            // 2 x [32][36]
    unsigned* Vt0 = Ks0 + 2 * KBUF;            // 2 x [64 e][20]
    float* maskSm = (float*)(Vt0 + 2 * VBUF);  // [CHSPLIT*32]

    int h = blockIdx.y;
    int z = blockIdx.z;
    int row0 = blockIdx.x * AQT;
    int t = threadIdx.x, w = t >> 5, lane = t & 31;
    int g = lane >> 2, c = lane & 3;
    int wrow = w * 32;

    int chBeg = z * CHSPLIT;
    int chEnd = min(chBeg + CHSPLIT, NCH);

    #pragma unroll 4
    for (int i = t; i < AQT * 8; i += 256) {
        int r = i >> 3, part = i & 7;
        uint4 q4 = *(const uint4*)(Q + (size_t)(row0 + r) * D_ + h * E_ + part * 8);
        *(uint4*)&Qs[r * QST + part * 4] = q4;
    }
    for (int i = t; i < CHSPLIT * ASC; i += 256) {
        int gs = chBeg * ASC + i;
        maskSm[i] = (gs < S_ && mask[gs] != 0) ? 0.f : -1e30f;
    }

    auto stageK = [&](int ch, int buf) {
        unsigned* Ks = Ks0 + buf * KBUF;
        int s0 = ch * ASC;
        #pragma unroll
        for (int i = t; i < ASC * 16; i += 256) {
            int s = i >> 4, chk = i & 15;
            int gs = s0 + s;
            cp8(&Ks[s * KST + chk * 2],
                K + (size_t)gs * D_ + h * E_ + chk * 4, gs < S_);
        }
        cp_commit();
    };
    auto loadV = [&](int ch) -> uint4 {
        int gs = ch * ASC + lane;
        if (gs < S_)
            return *(const uint4*)(V + (size_t)gs * D_ + h * E_ + w * 8);
        return make_uint4(0u, 0u, 0u, 0u);
    };
    auto storeV = [&](uint4 v, int buf) {
        __half* Vth = (__half*)(Vt0 + buf * VBUF);
        const __half* hv = (const __half*)&v;
        #pragma unroll
        for (int j = 0; j < 8; j++)
            Vth[(w * 8 + j) * (VST * 2) + lane] = hv[j];
    };

    float mA[2] = {-1e30f, -1e30f}, mB[2] = {-1e30f, -1e30f};
    float lA[2] = {0.f, 0.f}, lB[2] = {0.f, 0.f};
    float acc[2][8][4];
    #pragma unroll
    for (int mt = 0; mt < 2; mt++)
        #pragma unroll
        for (int nt = 0; nt < 8; nt++)
            #pragma unroll
            for (int k = 0; k < 4; k++) acc[mt][nt][k] = 0.f;

    {
        uint4 v0 = loadV(chBeg);
        stageK(chBeg, 0);
        cp_wait<0>();
        storeV(v0, 0);
    }
    __syncthreads();

    for (int ch = chBeg; ch < chEnd; ch++) {
        int buf = (ch - chBeg) & 1;
        bool more = (ch + 1 < chEnd);
        uint4 vnext;
        if (more) {
            vnext = loadV(ch + 1);
            stageK(ch + 1, buf ^ 1);
        }

        const unsigned* Ks = Ks0 + buf * KBUF;
        const unsigned* Vt = Vt0 + buf * VBUF;
        const float* maskAdd = maskSm + (ch - chBeg) * ASC;

        float sc[2][4][4];
        #pragma unroll
        for (int mt = 0; mt < 2; mt++)
            #pragma unroll
            for (int nt = 0; nt < 4; nt++)
                #pragma unroll
                for (int k = 0; k < 4; k++) sc[mt][nt][k] = 0.f;

        #pragma unroll
        for (int ks = 0; ks < 4; ks++) {
            int kk = ks * 8;
            unsigned a[2][4];
            #pragma unroll
            for (int mt = 0; mt < 2; mt++) {
                int base = wrow + mt * 16;
                a[mt][0] = Qs[(base + g)     * QST + kk + c];
                a[mt][1] = Qs[(base + g + 8) * QST + kk + c];
                a[mt][2] = Qs[(base + g)     * QST + kk + 4 + c];
                a[mt][3] = Qs[(base + g + 8) * QST + kk + 4 + c];
            }
            #pragma unroll
            for (int nt = 0; nt < 4; nt++) {
                int n0 = nt * 8;
                unsigned b0 = Ks[(n0 + g) * KST + kk + c];
                unsigned b1 = Ks[(n0 + g) * KST + kk + 4 + c];
                mma_f16(sc[0][nt], a[0], b0, b1);
                mma_f16(sc[1][nt], a[1], b0, b1);
            }
        }

        // ---- online softmax in log2 domain ----
        #pragma unroll
        for (int mt = 0; mt < 2; mt++) {
            float mxA = -1e30f, mxB = -1e30f;
            #pragma unroll
            for (int nt = 0; nt < 4; nt++) {
                int j0 = nt * 8 + 2 * c;
                float ma0 = maskAdd[j0], ma1 = maskAdd[j0 + 1];
                sc[mt][nt][0] = sc[mt][nt][0] * SCL + ma0;
                sc[mt][nt][1] = sc[mt][nt][1] * SCL + ma1;
                sc[mt][nt][2] = sc[mt][nt][2] * SCL + ma0;
                sc[mt][nt][3] = sc[mt][nt][3] * SCL + ma1;
                mxA = fmaxf(mxA, fmaxf(sc[mt][nt][0], sc[mt][nt][1]));
                mxB = fmaxf(mxB, fmaxf(sc[mt][nt][2], sc[mt][nt][3]));
            }
            mxA = fmaxf(mxA, __shfl_xor_sync(0xffffffffu, mxA, 1));
            mxA = fmaxf(mxA, __shfl_xor_sync(0xffffffffu, mxA, 2));
            mxB = fmaxf(mxB, __shfl_xor_sync(0xffffffffu, mxB, 1));
            mxB = fmaxf(mxB, __shfl_xor_sync(0xffffffffu, mxB, 2));

            float mnA = fmaxf(mA[mt], mxA);
            float mnB = fmaxf(mB[mt], mxB);
            float corrA = exp2f(mA[mt] - mnA);
            float corrB = exp2f(mB[mt] - mnB);
            mA[mt] = mnA; mB[mt] = mnB;

            float psA = 0.f, psB = 0.f;
            #pragma unroll
            for (int nt = 0; nt < 4; nt++) {
                float p0 = exp2f(sc[mt][nt][0] - mnA);
                float p1 = exp2f(sc[mt][nt][1] - mnA);
                float p2 = exp2f(sc[mt][nt][2] - mnB);
                float p3 = exp2f(sc[mt][nt][3] - mnB);
                psA += p0 + p1; psB += p2 + p3;
                sc[mt][nt][0] = p0; sc[mt][nt][1] = p1;
                sc[mt][nt][2] = p2; sc[mt][nt][3] = p3;
            }
            psA += __shfl_xor_sync(0xffffffffu, psA, 1);
            psA += __shfl_xor_sync(0xffffffffu, psA, 2);
            psB += __shfl_xor_sync(0xffffffffu, psB, 1);
            psB += __shfl_xor_sync(0xffffffffu, psB, 2);
            lA[mt] = lA[mt] * corrA + psA;
            lB[mt] = lB[mt] * corrB + psB;
            #pragma unroll
            for (int nt = 0; nt < 8; nt++) {
                acc[mt][nt][0] *= corrA; acc[mt][nt][1] *= corrA;
                acc[mt][nt][2] *= corrB; acc[mt][nt][3] *= corrB;
            }
        }

        #pragma unroll
        for (int ks = 0; ks < 2; ks++) {
            int kk = ks * 8;
            int t0 = ks * 2, t1 = t0 + 1;
            unsigned aP[2][4];
            #pragma unroll
            for (int mt = 0; mt < 2; mt++) {
                aP[mt][0] = packh2(sc[mt][t0][0], sc[mt][t0][1]);
                aP[mt][1] = packh2(sc[mt][t0][2], sc[mt][t0][3]);
                aP[mt][2] = packh2(sc[mt][t1][0], sc[mt][t1][1]);
                aP[mt][3] = packh2(sc[mt][t1][2], sc[mt][t1][3]);
            }
            #pragma unroll
            for (int nt = 0; nt < 8; nt++) {
                int e0 = nt * 8;
                unsigned b0 = Vt[(e0 + g) * VST + kk + c];
                unsigned b1 = Vt[(e0 + g) * VST + kk + 4 + c];
                mma_f16(acc[0][nt], aP[0], b0, b1);
                mma_f16(acc[1][nt], aP[1], b0, b1);
            }
        }

        if (more) {
            cp_wait<0>();
            storeV(vnext, buf ^ 1);
        }
        __syncthreads();
    }

    // epilogue: half unnormalized acc + fp32 (m[log2], l)
    #pragma unroll
    for (int mt = 0; mt < 2; mt++) {
        int rA = row0 + wrow + mt * 16 + g;
        int rB = rA + 8;
        __half* obase = Oacc + (size_t)z * MQ * D_;
        #pragma unroll
        for (int nt = 0; nt < 8; nt++) {
            int col = h * E_ + nt * 8 + 2 * c;
            *(unsigned*)&obase[(size_t)rA * D_ + col] = packh2(acc[mt][nt][0], acc[mt][nt][1]);
            *(unsigned*)&obase[(size_t)rB * D_ + col] = packh2(acc[mt][nt][2], acc[mt][nt][3]);
        }
        if (c == 0) {
            size_t iA = ((size_t)(z * MQ + rA) * H_ + h) * 2;
            size_t iB = ((size_t)(z * MQ + rB) * H_ + h) * 2;
            ML[iA]     = mA[mt]; ML[iA + 1] = lA[mt];
            ML[iB]     = mB[mt]; ML[iB + 1] = lB[mt];
        }
    }
}

// ---------------------------------------------------------------------------
// Split-KV combine + mean-pool v3: grid (BLn, 3) = 768 blocks; block (bl, dz)
// covers d in [dz*256, dz*256+256) = 4 heads. 32 threads precompute the 32
// (tq,h) weight triples; 256 threads emit one d each (pure FMA).
// ---------------------------------------------------------------------------
__global__ void combine_pool_kernel(const __half* __restrict__ Oacc,
                                    const float* __restrict__ ML,
                                    __half* __restrict__ P) {
    __shared__ float wS[TQn * 4 * 3];    // [tq*4 + (h-h0)][3]
    int bl = blockIdx.x;
    int dz = blockIdx.y;
    int h0 = dz * 4;                     // first head of this d-chunk
    int t = threadIdx.x;

    if (t < TQn * 4) {
        int tq = t >> 2, hl = t & 3;
        int h = h0 + hl;
        int row = bl * TQn + tq;
        size_t i0 = ((size_t)(0 * MQ + row) * H_ + h) * 2;
        size_t i1 = ((size_t)(1 * MQ + row) * H_ + h) * 2;
        size_t i2 = ((size_t)(2 * MQ + row) * H_ + h) * 2;
        float m0 = ML[i0], l0 = ML[i0 + 1];
        float m1 = ML[i1], l1 = ML[i1 + 1];
        float m2 = ML[i2], l2 = ML[i2 + 1];
        float M = fmaxf(m0, fmaxf(m1, m2));
        float w0 = exp2f(m0 - M), w1 = exp2f(m1 - M), w2 = exp2f(m2 - M);
        float inv = 1.0f / (l0 * w0 + l1 * w1 + l2 * w2);
        wS[t * 3 + 0] = w0 * inv * (1.0f / TQn);
        wS[t * 3 + 1] = w1 * inv * (1.0f / TQn);
        wS[t * 3 + 2] = w2 * inv * (1.0f / TQn);
    }
    __syncthreads();

    int d = dz * 256 + t;
    int hl = (t >> 6);                   // local head index 0..3
    float s = 0.f;
    #pragma unroll
    for (int tq = 0; tq < TQn; tq++) {
        int row = bl * TQn + tq;
        const float* wp = &wS[(tq * 4 + hl) * 3];
        float a0 = __half2float(Oacc[(size_t)(0 * MQ + row) * D_ + d]);
        float a1 = __half2float(Oacc[(size_t)(1 * MQ + row) * D_ + d]);
        float a2 = __half2float(Oacc[(size_t)(2 * MQ + row) * D_ + d]);
        s += a0 * wp[0] + a1 * wp[1] + a2 * wp[2];
    }
    P[(size_t)bl * D_ + d] = __float2half_rn(s);
}

// ---------------------------------------------------------------------------
extern "C" void kernel_launch(void* const* d_in, const int* in_sizes, int n_in,
                              void* d_out, int out_size) {
    const float* target     = (const float*)d_in[0];
    const float* key_bank   = (const float*)d_in[1];
    const float* value_bank = (const float*)d_in[2];
    const int*   bank_mask  = (const int*)  d_in[3];
    const float* Wq = (const float*)d_in[4];
    const float* bq = (const float*)d_in[5];
    const float* Wk = (const float*)d_in[6];
    const float* bk = (const float*)d_in[7];
    const float* Wv = (const float*)d_in[8];
    const float* bv = (const float*)d_in[9];
    const float* Wo = (const float*)d_in[10];
    const float* bo = (const float*)d_in[11];
    const float* gq = (const float*)d_in[12];
    const float* betaq = (const float*)d_in[13];
    const float* gkv = (const float*)d_in[14];
    const float* betakv = (const float*)d_in[15];
    float* out = (float*)d_out;

    __half *Xq, *Xk, *Xv, *Qb, *Kb, *Vb, *Oacc, *Pool;
    float *ML;
    cudaGetSymbolAddress((void**)&Xq,  g_Xq);
    cudaGetSymbolAddress((void**)&Xk,  g_Xk);
    cudaGetSymbolAddress((void**)&Xv,  g_Xv);
    cudaGetSymbolAddress((void**)&Qb,  g_Qb);
    cudaGetSymbolAddress((void**)&Kb,  g_Kb);
    cudaGetSymbolAddress((void**)&Vb,  g_Vb);
    cudaGetSymbolAddress((void**)&Oacc, g_Oacc);
    cudaGetSymbolAddress((void**)&ML,  g_ML);
    cudaGetSymbolAddress((void**)&Pool, g_Pool);

    cudaFuncSetAttribute(attn_f16,
                         cudaFuncAttributeMaxDynamicSharedMemorySize, ATTN_SMEM);

    // 1. Fused LayerNorms (half outputs)
    ln3_kernel<<<MQ + 2 * S_, 256>>>(target, Xq, gq, betaq,
                                     key_bank, value_bank, Xk, Xv, gkv, betakv);

    // 2. Q/K/V projections (fp32 weights, half outputs)
    gemm3_f16<<<dim3(D_ / 128, 16, 3), 256>>>(
        Xq, Wq, bq, Qb, MQ,
        Xk, Wk, bk, Kb, S_,
        Xv, Wv, bv, Vb, S_, 1);

    // 3. Attention: fp16 mma, exp2 softmax, split-KV x3, one wave
    attn_f16<<<dim3(MQ / AQT, H_, NSPLIT), 256, ATTN_SMEM>>>(
        Qb, Kb, Vb, bank_mask, Oacc, ML);

    // 4. Combine + mean-pool: 768 blocks, shared weights
    combine_pool_kernel<<<dim3(BLn, 3), 256>>>(Oacc, ML, Pool);

    // 5. Output projection (fp32 out)
    gemm3_f16<<<dim3(D_ / 128, 2, 1), 256>>>(
        Pool, Wo, bo, out, BLn,
        Pool, Wo, bo, out, BLn,
        Pool, Wo, bo, out, BLn, 0);
}